// round 2
// baseline (speedup 1.0000x reference)
#include <cuda_runtime.h>
#include <cstdint>
#include <math.h>

#define BATCH 8
#define NA 131072            // anchors per batch (2^17)
#define NPRE 6000            // PRE_NMS_LIMIT
#define NB 94                // ceil(NPRE/64)
#define NPROP 1000
#define CAND_CAP 8192
#define HBINS 131072         // key >> 15 fits in [0, 131072)
#define NMS_THR 0.7f

// ---------------- device scratch (static, no allocation) ----------------
__device__ unsigned int       g_keys[BATCH * NA];
__device__ unsigned int       g_hist[BATCH * HBINS];
__device__ int                g_cutbin[BATCH];
__device__ int                g_cand_cnt[BATCH];
__device__ unsigned long long g_cand[BATCH * CAND_CAP];
__device__ float4             g_boxes[BATCH * NPRE];
__device__ unsigned long long g_mask[(size_t)BATCH * NPRE * NB];
__device__ unsigned char      g_keep[BATCH * NPRE];

// ---------------- helpers ----------------
static __device__ __forceinline__ void cp_async8(unsigned int smem, const void* g) {
    asm volatile("cp.async.ca.shared.global [%0], [%1], 8;" :: "r"(smem), "l"(g) : "memory");
}
static __device__ __forceinline__ void cp_commit() {
    asm volatile("cp.async.commit_group;" ::: "memory");
}
static __device__ __forceinline__ void cp_wait15() {
    asm volatile("cp.async.wait_group 15;" ::: "memory");
}

// ---------------- 0: zero scratch ----------------
__global__ void zero_kernel() {
    int n = BATCH * HBINS;
    for (int i = blockIdx.x * blockDim.x + threadIdx.x; i < n; i += gridDim.x * blockDim.x)
        g_hist[i] = 0u;
    if (blockIdx.x == 0 && threadIdx.x < BATCH) g_cand_cnt[threadIdx.x] = 0;
}

// ---------------- 1: keys + histogram ----------------
__global__ void hist_kernel(const float* __restrict__ probs) {
    int gid = blockIdx.x * blockDim.x + threadIdx.x;
    if (gid >= BATCH * NA) return;
    unsigned int u = __float_as_uint(probs[2 * (size_t)gid + 1]);
    // monotone transform (handles negatives too, though scores are >= 0)
    unsigned int key = u ^ ((unsigned int)((int)u >> 31) | 0x80000000u);
    g_keys[gid] = key;
    int b = gid >> 17;
    atomicAdd(&g_hist[b * HBINS + (key >> 15)], 1u);
}

// ---------------- 2: find cutoff bin (suffix counts) ----------------
__global__ void cutoff_kernel() {
    int b = blockIdx.x, t = threadIdx.x;           // 1024 threads, 128 bins each
    __shared__ unsigned int S[1024];
    const unsigned int* H = g_hist + (size_t)b * HBINS;
    int base = t * 128;
    unsigned int s = 0;
    for (int k = 0; k < 128; ++k) s += H[base + k];
    S[t] = s;
    __syncthreads();
    for (int off = 1; off < 1024; off <<= 1) {
        unsigned int v = (t + off < 1024) ? S[t + off] : 0u;
        __syncthreads();
        S[t] += v;
        __syncthreads();
    }
    unsigned int nextS = (t < 1023) ? S[t + 1] : 0u;
    if (S[t] >= NPRE && nextS < NPRE) {
        unsigned int run = nextS;
        int cut = base;
        for (int k = 127; k >= 0; --k) {
            run += H[base + k];
            if (run >= NPRE) { cut = base + k; break; }
        }
        g_cutbin[b] = cut;
    }
}

// ---------------- 3: compact candidates ----------------
__global__ void compact_kernel() {
    int gid = blockIdx.x * blockDim.x + threadIdx.x;
    if (gid >= BATCH * NA) return;
    int b = gid >> 17;
    unsigned int a = (unsigned int)(gid & (NA - 1));
    unsigned int key = g_keys[gid];
    if ((int)(key >> 15) >= g_cutbin[b]) {
        int pos = atomicAdd(&g_cand_cnt[b], 1);
        if (pos < CAND_CAP)
            g_cand[b * CAND_CAP + pos] =
                ((unsigned long long)key << 32) | (unsigned long long)(~a);
    }
}

// ---------------- 4: bitonic sort (desc) + box decode ----------------
__global__ void sort_box_kernel(const float* __restrict__ bbox,
                                const float* __restrict__ anchors) {
    extern __shared__ unsigned long long sh[];
    int b = blockIdx.x, t = threadIdx.x;           // 1024 threads
    int cnt = g_cand_cnt[b]; if (cnt > CAND_CAP) cnt = CAND_CAP;
    for (int i = t; i < CAND_CAP; i += blockDim.x)
        sh[i] = (i < cnt) ? g_cand[b * CAND_CAP + i] : 0ULL;
    __syncthreads();
    for (int k = 2; k <= CAND_CAP; k <<= 1) {
        for (int j = k >> 1; j > 0; j >>= 1) {
            for (int i = t; i < CAND_CAP; i += blockDim.x) {
                int l = i ^ j;
                if (l > i) {
                    unsigned long long x = sh[i], y = sh[l];
                    bool seg = (i & k) != 0;        // descending network
                    if (seg ? (x > y) : (x < y)) { sh[i] = y; sh[l] = x; }
                }
            }
            __syncthreads();
        }
    }
    // decode boxes for top NPRE (sorted score desc, ties by index asc)
    for (int r = t; r < NPRE; r += blockDim.x) {
        unsigned long long v = sh[r];
        unsigned int a = ~(unsigned int)(v & 0xffffffffULL);
        size_t src = (((size_t)b << 17) + a) * 4;
        float d0 = bbox[src + 0] * 0.1f;
        float d1 = bbox[src + 1] * 0.1f;
        float d2 = bbox[src + 2] * 0.2f;
        float d3 = bbox[src + 3] * 0.2f;
        float a0 = anchors[src + 0], a1 = anchors[src + 1];
        float a2 = anchors[src + 2], a3 = anchors[src + 3];
        float h = a2 - a0, w = a3 - a1;
        float cy = a0 + 0.5f * h + d0 * h;
        float cx = a1 + 0.5f * w + d1 * w;
        float h2 = h * expf(d2);
        float w2 = w * expf(d3);
        float y1 = cy - 0.5f * h2;
        float x1 = cx - 0.5f * w2;
        float y2 = y1 + h2;
        float x2 = x1 + w2;
        y1 = fminf(fmaxf(y1, 0.f), 1.f);
        x1 = fminf(fmaxf(x1, 0.f), 1.f);
        y2 = fminf(fmaxf(y2, 0.f), 1.f);
        x2 = fminf(fmaxf(x2, 0.f), 1.f);
        g_boxes[b * NPRE + r] = make_float4(y1, x1, y2, x2);
    }
}

// ---------------- 5: suppression bitmask (i suppresses j>i) ----------------
// grid (47 rowblks of 128 rows, 94 colblks of 64 cols, BATCH), 64 threads, 2 rows/thread
__global__ void mask_kernel() {
    int rowblk = blockIdx.x, colblk = blockIdx.y, b = blockIdx.z;
    int t = threadIdx.x;
    int i0 = rowblk * 128 + t;
    int i1 = i0 + 64;
    unsigned long long* mrow = g_mask + (size_t)b * NPRE * NB;
    if (colblk < 2 * rowblk) {                      // strictly below diagonal
        if (i0 < NPRE) mrow[(size_t)i0 * NB + colblk] = 0ULL;
        if (i1 < NPRE) mrow[(size_t)i1 * NB + colblk] = 0ULL;
        return;
    }
    __shared__ float4 s_box[64];
    __shared__ float  s_area[64];
    int jj0 = colblk * 64;
    {
        int jj = jj0 + t;
        float4 c = (jj < NPRE) ? g_boxes[b * NPRE + jj] : make_float4(4.f, 4.f, 3.f, 3.f);
        s_box[t] = c;
        s_area[t] = (c.z - c.x) * (c.w - c.y);
    }
    __syncthreads();
    float4 rb0 = (i0 < NPRE) ? g_boxes[b * NPRE + i0] : make_float4(4.f, 4.f, 3.f, 3.f);
    float4 rb1 = (i1 < NPRE) ? g_boxes[b * NPRE + i1] : make_float4(4.f, 4.f, 3.f, 3.f);
    float ar0 = (rb0.z - rb0.x) * (rb0.w - rb0.y);
    float ar1 = (rb1.z - rb1.x) * (rb1.w - rb1.y);
    unsigned long long bits0 = 0ULL, bits1 = 0ULL;
#pragma unroll 4
    for (int j = 0; j < 64; ++j) {
        float4 c = s_box[j];
        float ca = s_area[j];
        int jj = jj0 + j;
        float dy0 = fminf(rb0.z, c.z) - fmaxf(rb0.x, c.x);
        float dx0 = fminf(rb0.w, c.w) - fmaxf(rb0.y, c.y);
        float dy1 = fminf(rb1.z, c.z) - fmaxf(rb1.x, c.x);
        float dx1 = fminf(rb1.w, c.w) - fmaxf(rb1.y, c.y);
        bool ov0 = (dy0 > 0.f) && (dx0 > 0.f) && (jj > i0);
        bool ov1 = (dy1 > 0.f) && (dx1 > 0.f) && (jj > i1);
        if (__any_sync(0xffffffffu, ov0 || ov1)) {
            if (ov0) {
                float inter = dy0 * dx0;
                float uni = fmaxf(ar0 + ca - inter, 1e-12f);
                if (__fdiv_rn(inter, uni) > NMS_THR) bits0 |= (1ULL << j);
            }
            if (ov1) {
                float inter = dy1 * dx1;
                float uni = fmaxf(ar1 + ca - inter, 1e-12f);
                if (__fdiv_rn(inter, uni) > NMS_THR) bits1 |= (1ULL << j);
            }
        }
    }
    if (i0 < NPRE) mrow[(size_t)i0 * NB + colblk] = bits0;
    if (i1 < NPRE) mrow[(size_t)i1 * NB + colblk] = bits1;
}

// ---------------- 6: sequential greedy scan (1 warp per batch) ----------------
__global__ void nms_scan_kernel() {
    int b = blockIdx.x, t = threadIdx.x;            // 32 threads
    __shared__ unsigned long long ring[16 * 96];    // 16-deep row ring, stride 96
    for (int k = t; k < 16 * 96; k += 32) ring[k] = 0ULL;
    __syncwarp();
    unsigned long long r0 = 0, r1 = 0, r2 = 0;      // remv words t, t+32, t+64
    unsigned int sbase = (unsigned int)__cvta_generic_to_shared(ring);
    const unsigned long long* mrow = g_mask + (size_t)b * NPRE * NB;
    // prologue: rows 0..15 in flight
    for (int r = 0; r < 16; ++r) {
        const unsigned long long* src = mrow + (size_t)r * NB;
        unsigned int dst = sbase + (unsigned int)((r * 96 + t) * 8);
        cp_async8(dst, src + t);
        cp_async8(dst + 32 * 8, src + t + 32);
        if (t < 30) cp_async8(dst + 64 * 8, src + t + 64);
        cp_commit();
    }
    for (int i = 0; i < NPRE; ++i) {
        cp_wait15();                                 // row i resident
        int wi = i >> 6;
        unsigned long long v = (wi < 32) ? r0 : (wi < 64) ? r1 : r2;
        unsigned long long wv = __shfl_sync(0xffffffffu, v, wi & 31);
        int supp = (int)((wv >> (i & 63)) & 1ULL);
        int slot = i & 15;
        if (!supp) {
            r0 |= ring[slot * 96 + t];
            r1 |= ring[slot * 96 + t + 32];
            r2 |= ring[slot * 96 + t + 64];          // words 94,95 stay zero
        }
        if (t == 0) g_keep[b * NPRE + i] = (unsigned char)(supp ^ 1);
        int r = i + 16;
        if (r < NPRE) {
            const unsigned long long* src = mrow + (size_t)r * NB;
            unsigned int dst = sbase + (unsigned int)(((r & 15) * 96 + t) * 8);
            cp_async8(dst, src + t);
            cp_async8(dst + 32 * 8, src + t + 32);
            if (t < 30) cp_async8(dst + 64 * 8, src + t + 64);
        }
        cp_commit();                                 // commit every iter (may be empty)
    }
}

// ---------------- 7: compact kept boxes -> output ----------------
__global__ void final_kernel(float* __restrict__ out) {
    int b = blockIdx.x, t = threadIdx.x;            // 1024 threads
    for (int k = t; k < NPROP * 4; k += blockDim.x) out[b * NPROP * 4 + k] = 0.f;
    __syncthreads();
    __shared__ int sc[1024];
    __shared__ int s_off;
    if (t == 0) s_off = 0;
    __syncthreads();
    for (int tile = 0; tile < 6; ++tile) {
        int i = tile * 1024 + t;
        int kp = (i < NPRE) ? (int)g_keep[b * NPRE + i] : 0;
        sc[t] = kp;
        __syncthreads();
        for (int d = 1; d < 1024; d <<= 1) {
            int v = (t >= d) ? sc[t - d] : 0;
            __syncthreads();
            sc[t] += v;
            __syncthreads();
        }
        int off = s_off;
        if (kp) {
            int rank = off + sc[t] - 1;
            if (rank < NPROP)
                ((float4*)out)[b * NPROP + rank] = g_boxes[b * NPRE + i];
        }
        __syncthreads();
        if (t == 1023) s_off = off + sc[1023];
        __syncthreads();
    }
}

// ---------------- launch ----------------
extern "C" void kernel_launch(void* const* d_in, const int* in_sizes, int n_in,
                              void* d_out, int out_size) {
    const float* probs   = (const float*)d_in[0];
    const float* bbox    = (const float*)d_in[1];
    const float* anchors = (const float*)d_in[2];
    float* out = (float*)d_out;

    zero_kernel<<<512, 1024>>>();
    hist_kernel<<<(BATCH * NA) / 256, 256>>>(probs);
    cutoff_kernel<<<BATCH, 1024>>>();
    compact_kernel<<<(BATCH * NA) / 256, 256>>>();
    cudaFuncSetAttribute(sort_box_kernel,
                         cudaFuncAttributeMaxDynamicSharedMemorySize, CAND_CAP * 8);
    sort_box_kernel<<<BATCH, 1024, CAND_CAP * 8>>>(bbox, anchors);
    mask_kernel<<<dim3(47, 94, BATCH), 64>>>();
    nms_scan_kernel<<<BATCH, 32>>>();
    final_kernel<<<BATCH, 1024>>>(out);
}

// round 3
// speedup vs baseline: 3.1030x; 3.1030x over previous
#include <cuda_runtime.h>
#include <cstdint>
#include <math.h>

#define BATCH 8
#define NA 131072            // anchors per batch (2^17)
#define NPRE 6000            // PRE_NMS_LIMIT
#define NB 94                // ceil(NPRE/64)  (fallback mask)
#define NPROP 1000
#define CAND_CAP 8192
#define HBINS 16384          // key >> 18
#define NMS_THR 0.7f
#define N1 1536              // phase-1 prefix rows
#define NB1 24               // N1/64

// ---------------- device scratch (static, no allocation) ----------------
__device__ unsigned int       g_keys[BATCH * NA];
__device__ unsigned int       g_hist[BATCH * HBINS];
__device__ int                g_cutbin[BATCH];
__device__ int                g_cand_cnt[BATCH];
__device__ unsigned long long g_cand[BATCH * CAND_CAP];
__device__ float4             g_boxes[BATCH * NPRE];
__device__ unsigned long long g_mask1[(size_t)BATCH * N1 * NB1];
__device__ unsigned long long g_mask[(size_t)BATCH * NPRE * NB];
__device__ unsigned char      g_keep[BATCH * NPRE];
__device__ int                g_done[BATCH];

// ---------------- helpers ----------------
static __device__ __forceinline__ void cp_async8(unsigned int smem, const void* g) {
    asm volatile("cp.async.ca.shared.global [%0], [%1], 8;" :: "r"(smem), "l"(g) : "memory");
}
static __device__ __forceinline__ void cp_commit() {
    asm volatile("cp.async.commit_group;" ::: "memory");
}
static __device__ __forceinline__ void cp_wait15() {
    asm volatile("cp.async.wait_group 15;" ::: "memory");
}

// ---------------- 0: zero scratch ----------------
__global__ void zero_kernel() {
    int n = BATCH * HBINS;
    for (int i = blockIdx.x * blockDim.x + threadIdx.x; i < n; i += gridDim.x * blockDim.x)
        g_hist[i] = 0u;
    int gid = blockIdx.x * blockDim.x + threadIdx.x;
    if (gid < BATCH * NPRE) g_keep[gid] = 0;
    if (gid < BATCH) { g_cand_cnt[gid] = 0; g_done[gid] = 0; }
}

// ---------------- 1: keys + histogram ----------------
__global__ void hist_kernel(const float* __restrict__ probs) {
    int gid = blockIdx.x * blockDim.x + threadIdx.x;
    if (gid >= BATCH * NA) return;
    float2 pv = ((const float2*)probs)[gid];
    unsigned int u = __float_as_uint(pv.y);
    unsigned int key = u ^ ((unsigned int)((int)u >> 31) | 0x80000000u);
    g_keys[gid] = key;
    int b = gid >> 17;
    atomicAdd(&g_hist[b * HBINS + (key >> 18)], 1u);
}

// ---------------- 2: find cutoff bin (suffix counts) ----------------
__global__ void cutoff_kernel() {
    int b = blockIdx.x, t = threadIdx.x;           // 1024 threads, 16 bins each
    __shared__ unsigned int S[1024];
    const unsigned int* H = g_hist + (size_t)b * HBINS;
    int base = t * 16;
    unsigned int s = 0;
    for (int k = 0; k < 16; ++k) s += H[base + k];
    S[t] = s;
    __syncthreads();
    for (int off = 1; off < 1024; off <<= 1) {
        unsigned int v = (t + off < 1024) ? S[t + off] : 0u;
        __syncthreads();
        S[t] += v;
        __syncthreads();
    }
    unsigned int nextS = (t < 1023) ? S[t + 1] : 0u;
    if (S[t] >= NPRE && nextS < NPRE) {
        unsigned int run = nextS;
        int cut = base;
        for (int k = 15; k >= 0; --k) {
            run += H[base + k];
            if (run >= NPRE) { cut = base + k; break; }
        }
        g_cutbin[b] = cut;
    }
}

// ---------------- 3: compact candidates ----------------
__global__ void compact_kernel() {
    int gid = blockIdx.x * blockDim.x + threadIdx.x;
    if (gid >= BATCH * NA) return;
    int b = gid >> 17;
    unsigned int a = (unsigned int)(gid & (NA - 1));
    unsigned int key = g_keys[gid];
    if ((int)(key >> 18) >= g_cutbin[b]) {
        int pos = atomicAdd(&g_cand_cnt[b], 1);
        if (pos < CAND_CAP)
            g_cand[b * CAND_CAP + pos] =
                ((unsigned long long)key << 32) | (unsigned long long)(~a);
    }
}

// ---------------- 4: bitonic sort (desc) + box decode ----------------
__global__ void sort_box_kernel(const float* __restrict__ bbox,
                                const float* __restrict__ anchors) {
    extern __shared__ unsigned long long sh[];
    int b = blockIdx.x, t = threadIdx.x;           // 1024 threads
    int cnt = g_cand_cnt[b]; if (cnt > CAND_CAP) cnt = CAND_CAP;
    for (int i = t; i < CAND_CAP; i += blockDim.x)
        sh[i] = (i < cnt) ? g_cand[b * CAND_CAP + i] : 0ULL;
    __syncthreads();
    for (int k = 2; k <= CAND_CAP; k <<= 1) {
        for (int j = k >> 1; j > 0; j >>= 1) {
            for (int i = t; i < CAND_CAP; i += blockDim.x) {
                int l = i ^ j;
                if (l > i) {
                    unsigned long long x = sh[i], y = sh[l];
                    bool seg = (i & k) != 0;        // descending network
                    if (seg ? (x > y) : (x < y)) { sh[i] = y; sh[l] = x; }
                }
            }
            __syncthreads();
        }
    }
    for (int r = t; r < NPRE; r += blockDim.x) {
        unsigned long long v = sh[r];
        unsigned int a = ~(unsigned int)(v & 0xffffffffULL);
        size_t src = (((size_t)b << 17) + a) * 4;
        float d0 = bbox[src + 0] * 0.1f;
        float d1 = bbox[src + 1] * 0.1f;
        float d2 = bbox[src + 2] * 0.2f;
        float d3 = bbox[src + 3] * 0.2f;
        float a0 = anchors[src + 0], a1 = anchors[src + 1];
        float a2 = anchors[src + 2], a3 = anchors[src + 3];
        float h = a2 - a0, w = a3 - a1;
        float cy = a0 + 0.5f * h + d0 * h;
        float cx = a1 + 0.5f * w + d1 * w;
        float h2 = h * expf(d2);
        float w2 = w * expf(d3);
        float y1 = cy - 0.5f * h2;
        float x1 = cx - 0.5f * w2;
        float y2 = y1 + h2;
        float x2 = x1 + w2;
        y1 = fminf(fmaxf(y1, 0.f), 1.f);
        x1 = fminf(fmaxf(x1, 0.f), 1.f);
        y2 = fminf(fmaxf(y2, 0.f), 1.f);
        x2 = fminf(fmaxf(x2, 0.f), 1.f);
        g_boxes[b * NPRE + r] = make_float4(y1, x1, y2, x2);
    }
}

// ---------------- common IoU tile body ----------------
static __device__ __forceinline__ void mask_tile(
    const float4* boxes_b, int i0, int i1, int jj0,
    unsigned long long& bits0, unsigned long long& bits1,
    int nlimit)
{
    __shared__ float4 s_box[64];
    __shared__ float  s_area[64];
    int t = threadIdx.x;
    {
        int jj = jj0 + t;
        float4 c = (jj < nlimit) ? boxes_b[jj] : make_float4(4.f, 4.f, 3.f, 3.f);
        s_box[t] = c;
        s_area[t] = (c.z - c.x) * (c.w - c.y);
    }
    __syncthreads();
    float4 rb0 = (i0 < nlimit) ? boxes_b[i0] : make_float4(4.f, 4.f, 3.f, 3.f);
    float4 rb1 = (i1 < nlimit) ? boxes_b[i1] : make_float4(4.f, 4.f, 3.f, 3.f);
    float ar0 = (rb0.z - rb0.x) * (rb0.w - rb0.y);
    float ar1 = (rb1.z - rb1.x) * (rb1.w - rb1.y);
    bits0 = 0ULL; bits1 = 0ULL;
#pragma unroll 4
    for (int j = 0; j < 64; ++j) {
        float4 c = s_box[j];
        float ca = s_area[j];
        int jj = jj0 + j;
        float dy0 = fminf(rb0.z, c.z) - fmaxf(rb0.x, c.x);
        float dx0 = fminf(rb0.w, c.w) - fmaxf(rb0.y, c.y);
        float dy1 = fminf(rb1.z, c.z) - fmaxf(rb1.x, c.x);
        float dx1 = fminf(rb1.w, c.w) - fmaxf(rb1.y, c.y);
        bool ov0 = (dy0 > 0.f) && (dx0 > 0.f) && (jj > i0);
        bool ov1 = (dy1 > 0.f) && (dx1 > 0.f) && (jj > i1);
        if (__any_sync(0xffffffffu, ov0 || ov1)) {
            if (ov0) {
                float inter = dy0 * dx0;
                float uni = fmaxf(ar0 + ca - inter, 1e-12f);
                if (__fdiv_rn(inter, uni) > NMS_THR) bits0 |= (1ULL << j);
            }
            if (ov1) {
                float inter = dy1 * dx1;
                float uni = fmaxf(ar1 + ca - inter, 1e-12f);
                if (__fdiv_rn(inter, uni) > NMS_THR) bits1 |= (1ULL << j);
            }
        }
    }
}

// ---------------- 5a: phase-1 mask over first N1 boxes ----------------
// grid (12 rowblks of 128, 24 colblks of 64, BATCH), 64 threads, 2 rows/thread
__global__ void mask1_kernel() {
    int rowblk = blockIdx.x, colblk = blockIdx.y, b = blockIdx.z;
    int t = threadIdx.x;
    int i0 = rowblk * 128 + t;
    int i1 = i0 + 64;
    unsigned long long* mrow = g_mask1 + (size_t)b * N1 * NB1;
    if (colblk < 2 * rowblk) {
        mrow[(size_t)i0 * NB1 + colblk] = 0ULL;
        mrow[(size_t)i1 * NB1 + colblk] = 0ULL;
        return;
    }
    unsigned long long bits0, bits1;
    mask_tile(g_boxes + b * NPRE, i0, i1, colblk * 64, bits0, bits1, N1);
    mrow[(size_t)i0 * NB1 + colblk] = bits0;
    mrow[(size_t)i1 * NB1 + colblk] = bits1;
}

// ---------------- 6a: phase-1 scan (1 warp per batch, N1 rows) ----------------
__global__ void nms_scan1_kernel() {
    int b = blockIdx.x, t = threadIdx.x;            // 32 threads
    __shared__ unsigned long long ring[16 * 32];
    for (int k = t; k < 16 * 32; k += 32) ring[k] = 0ULL;
    __syncwarp();
    unsigned long long r0 = 0;                      // remv word t (t<24 meaningful)
    unsigned int sbase = (unsigned int)__cvta_generic_to_shared(ring);
    const unsigned long long* mrow = g_mask1 + (size_t)b * N1 * NB1;
    for (int r = 0; r < 16; ++r) {
        if (t < NB1) cp_async8(sbase + (unsigned int)((r * 32 + t) * 8),
                               mrow + (size_t)r * NB1 + t);
        cp_commit();
    }
    int cnt = 0;
    for (int i = 0; i < N1; ++i) {
        cp_wait15();
        int wi = i >> 6;
        unsigned long long wv = __shfl_sync(0xffffffffu, r0, wi);
        int supp = (int)((wv >> (i & 63)) & 1ULL);
        int slot = i & 15;
        if (!supp) r0 |= ring[slot * 32 + t];
        if (t == 0) { g_keep[b * NPRE + i] = (unsigned char)(supp ^ 1); cnt += supp ^ 1; }
        int r = i + 16;
        if (r < N1 && t < NB1)
            cp_async8(sbase + (unsigned int)(((r & 15) * 32 + t) * 8),
                      mrow + (size_t)r * NB1 + t);
        cp_commit();
    }
    if (t == 0) g_done[b] = (cnt >= NPROP) ? 1 : 0;
}

// ---------------- 5b: fallback full mask (guarded) ----------------
__global__ void mask_kernel() {
    int b = blockIdx.z;
    if (g_done[b]) return;
    int rowblk = blockIdx.x, colblk = blockIdx.y;
    int t = threadIdx.x;
    int i0 = rowblk * 128 + t;
    int i1 = i0 + 64;
    unsigned long long* mrow = g_mask + (size_t)b * NPRE * NB;
    if (colblk < 2 * rowblk) {
        if (i0 < NPRE) mrow[(size_t)i0 * NB + colblk] = 0ULL;
        if (i1 < NPRE) mrow[(size_t)i1 * NB + colblk] = 0ULL;
        return;
    }
    unsigned long long bits0, bits1;
    mask_tile(g_boxes + b * NPRE, i0, i1, colblk * 64, bits0, bits1, NPRE);
    if (i0 < NPRE) mrow[(size_t)i0 * NB + colblk] = bits0;
    if (i1 < NPRE) mrow[(size_t)i1 * NB + colblk] = bits1;
}

// ---------------- 6b: fallback full scan (guarded) ----------------
__global__ void nms_scan_kernel() {
    int b = blockIdx.x, t = threadIdx.x;            // 32 threads
    if (g_done[b]) return;
    __shared__ unsigned long long ring[16 * 96];
    for (int k = t; k < 16 * 96; k += 32) ring[k] = 0ULL;
    __syncwarp();
    unsigned long long r0 = 0, r1 = 0, r2 = 0;
    unsigned int sbase = (unsigned int)__cvta_generic_to_shared(ring);
    const unsigned long long* mrow = g_mask + (size_t)b * NPRE * NB;
    for (int r = 0; r < 16; ++r) {
        const unsigned long long* src = mrow + (size_t)r * NB;
        unsigned int dst = sbase + (unsigned int)((r * 96 + t) * 8);
        cp_async8(dst, src + t);
        cp_async8(dst + 32 * 8, src + t + 32);
        if (t < 30) cp_async8(dst + 64 * 8, src + t + 64);
        cp_commit();
    }
    for (int i = 0; i < NPRE; ++i) {
        cp_wait15();
        int wi = i >> 6;
        unsigned long long v = (wi < 32) ? r0 : (wi < 64) ? r1 : r2;
        unsigned long long wv = __shfl_sync(0xffffffffu, v, wi & 31);
        int supp = (int)((wv >> (i & 63)) & 1ULL);
        int slot = i & 15;
        if (!supp) {
            r0 |= ring[slot * 96 + t];
            r1 |= ring[slot * 96 + t + 32];
            r2 |= ring[slot * 96 + t + 64];
        }
        if (t == 0) g_keep[b * NPRE + i] = (unsigned char)(supp ^ 1);
        int r = i + 16;
        if (r < NPRE) {
            const unsigned long long* src = mrow + (size_t)r * NB;
            unsigned int dst = sbase + (unsigned int)(((r & 15) * 96 + t) * 8);
            cp_async8(dst, src + t);
            cp_async8(dst + 32 * 8, src + t + 32);
            if (t < 30) cp_async8(dst + 64 * 8, src + t + 64);
        }
        cp_commit();
    }
}

// ---------------- 7: compact kept boxes -> output ----------------
__global__ void final_kernel(float* __restrict__ out) {
    int b = blockIdx.x, t = threadIdx.x;            // 1024 threads
    for (int k = t; k < NPROP * 4; k += blockDim.x) out[b * NPROP * 4 + k] = 0.f;
    __syncthreads();
    __shared__ int sc[1024];
    __shared__ int s_off;
    if (t == 0) s_off = 0;
    __syncthreads();
    for (int tile = 0; tile < 6; ++tile) {
        int i = tile * 1024 + t;
        int kp = (i < NPRE) ? (int)g_keep[b * NPRE + i] : 0;
        sc[t] = kp;
        __syncthreads();
        for (int d = 1; d < 1024; d <<= 1) {
            int v = (t >= d) ? sc[t - d] : 0;
            __syncthreads();
            sc[t] += v;
            __syncthreads();
        }
        int off = s_off;
        if (kp) {
            int rank = off + sc[t] - 1;
            if (rank < NPROP)
                ((float4*)out)[b * NPROP + rank] = g_boxes[b * NPRE + i];
        }
        __syncthreads();
        if (t == 1023) s_off = off + sc[1023];
        __syncthreads();
    }
}

// ---------------- launch ----------------
extern "C" void kernel_launch(void* const* d_in, const int* in_sizes, int n_in,
                              void* d_out, int out_size) {
    const float* probs   = (const float*)d_in[0];
    const float* bbox    = (const float*)d_in[1];
    const float* anchors = (const float*)d_in[2];
    float* out = (float*)d_out;

    zero_kernel<<<256, 1024>>>();
    hist_kernel<<<(BATCH * NA) / 256, 256>>>(probs);
    cutoff_kernel<<<BATCH, 1024>>>();
    compact_kernel<<<(BATCH * NA) / 256, 256>>>();
    cudaFuncSetAttribute(sort_box_kernel,
                         cudaFuncAttributeMaxDynamicSharedMemorySize, CAND_CAP * 8);
    sort_box_kernel<<<BATCH, 1024, CAND_CAP * 8>>>(bbox, anchors);
    mask1_kernel<<<dim3(12, 24, BATCH), 64>>>();
    nms_scan1_kernel<<<BATCH, 32>>>();
    mask_kernel<<<dim3(47, 94, BATCH), 64>>>();     // no-op when done
    nms_scan_kernel<<<BATCH, 32>>>();               // no-op when done
    final_kernel<<<BATCH, 1024>>>(out);
}

// round 4
// speedup vs baseline: 4.4809x; 1.4440x over previous
#include <cuda_runtime.h>
#include <cstdint>
#include <math.h>

#define BATCH 8
#define NA 131072            // anchors per batch (2^17)
#define NPRE 6000            // PRE_NMS_LIMIT
#define NB 94                // ceil(NPRE/64)  (fallback mask)
#define NPROP 1000
#define CAND_CAP 8192
#define HBINS 16384          // key >> 18
#define NMS_THR 0.7f
#define N1 1536              // phase-1 prefix rows
#define ECAP 6144            // edge list capacity per batch
#define PASSMAX 64

// ---------------- device scratch (static, no allocation) ----------------
__device__ unsigned int       g_hist[BATCH * HBINS];
__device__ int                g_cutbin[BATCH];
__device__ int                g_cand_cnt[BATCH];
__device__ unsigned long long g_cand[BATCH * CAND_CAP];
__device__ float4             g_boxes[BATCH * NPRE];
__device__ int                g_ecnt[BATCH];
__device__ unsigned int       g_edges[BATCH * ECAP];
__device__ unsigned long long g_mask[(size_t)BATCH * NPRE * NB];
__device__ unsigned char      g_keep[BATCH * NPRE];
__device__ int                g_done[BATCH];

// ---------------- helpers ----------------
static __device__ __forceinline__ void cp_async8(unsigned int smem, const void* g) {
    asm volatile("cp.async.ca.shared.global [%0], [%1], 8;" :: "r"(smem), "l"(g) : "memory");
}
static __device__ __forceinline__ void cp_commit() {
    asm volatile("cp.async.commit_group;" ::: "memory");
}
static __device__ __forceinline__ void cp_wait15() {
    asm volatile("cp.async.wait_group 15;" ::: "memory");
}
static __device__ __forceinline__ unsigned int score_key(float s) {
    unsigned int u = __float_as_uint(s);
    return u ^ ((unsigned int)((int)u >> 31) | 0x80000000u);
}

// ---------------- 0: zero scratch ----------------
__global__ void zero_kernel() {
    int gid = blockIdx.x * blockDim.x + threadIdx.x;
    int stride = gridDim.x * blockDim.x;
    for (int i = gid; i < BATCH * HBINS; i += stride) g_hist[i] = 0u;
    if (gid < BATCH * NPRE) g_keep[gid] = 0;
    if (gid < BATCH) { g_cand_cnt[gid] = 0; g_done[gid] = 0; g_ecnt[gid] = 0; }
}

// ---------------- 1: histogram of keys ----------------
__global__ void hist_kernel(const float* __restrict__ probs) {
    int gid = blockIdx.x * blockDim.x + threadIdx.x;
    int stride = gridDim.x * blockDim.x;
    const float2* p2 = (const float2*)probs;
    for (int i = gid; i < BATCH * NA; i += stride) {
        unsigned int key = score_key(p2[i].y);
        int b = i >> 17;
        atomicAdd(&g_hist[b * HBINS + (key >> 18)], 1u);
    }
}

// ---------------- 2: find cutoff bin (suffix counts) ----------------
__global__ void cutoff_kernel() {
    int b = blockIdx.x, t = threadIdx.x;           // 1024 threads, 16 bins each
    __shared__ unsigned int S[1024];
    const unsigned int* H = g_hist + (size_t)b * HBINS;
    int base = t * 16;
    unsigned int s = 0;
    for (int k = 0; k < 16; ++k) s += H[base + k];
    S[t] = s;
    __syncthreads();
    for (int off = 1; off < 1024; off <<= 1) {
        unsigned int v = (t + off < 1024) ? S[t + off] : 0u;
        __syncthreads();
        S[t] += v;
        __syncthreads();
    }
    unsigned int nextS = (t < 1023) ? S[t + 1] : 0u;
    if (S[t] >= NPRE && nextS < NPRE) {
        unsigned int run = nextS;
        int cut = base;
        for (int k = 15; k >= 0; --k) {
            run += H[base + k];
            if (run >= NPRE) { cut = base + k; break; }
        }
        g_cutbin[b] = cut;
    }
}

// ---------------- 3: compact candidates (recompute key from probs) ----------------
__global__ void compact_kernel(const float* __restrict__ probs) {
    int gid = blockIdx.x * blockDim.x + threadIdx.x;
    int stride = gridDim.x * blockDim.x;
    const float2* p2 = (const float2*)probs;
    for (int i = gid; i < BATCH * NA; i += stride) {
        unsigned int key = score_key(p2[i].y);
        int b = i >> 17;
        if ((int)(key >> 18) >= g_cutbin[b]) {
            int pos = atomicAdd(&g_cand_cnt[b], 1);
            if (pos < CAND_CAP) {
                unsigned int a = (unsigned int)(i & (NA - 1));
                g_cand[b * CAND_CAP + pos] =
                    ((unsigned long long)key << 32) | (unsigned long long)(~a);
            }
        }
    }
}

// ---------------- 4: bitonic sort (desc) + box decode ----------------
__global__ void sort_box_kernel(const float* __restrict__ bbox,
                                const float* __restrict__ anchors) {
    extern __shared__ unsigned long long sh[];
    int b = blockIdx.x, t = threadIdx.x;           // 1024 threads
    int cnt = g_cand_cnt[b]; if (cnt > CAND_CAP) cnt = CAND_CAP;
    for (int i = t; i < CAND_CAP; i += blockDim.x)
        sh[i] = (i < cnt) ? g_cand[b * CAND_CAP + i] : 0ULL;
    __syncthreads();
    for (int k = 2; k <= CAND_CAP; k <<= 1) {
        for (int j = k >> 1; j > 0; j >>= 1) {
            for (int i = t; i < CAND_CAP; i += blockDim.x) {
                int l = i ^ j;
                if (l > i) {
                    unsigned long long x = sh[i], y = sh[l];
                    bool seg = (i & k) != 0;        // descending network
                    if (seg ? (x > y) : (x < y)) { sh[i] = y; sh[l] = x; }
                }
            }
            __syncthreads();
        }
    }
    for (int r = t; r < NPRE; r += blockDim.x) {
        unsigned long long v = sh[r];
        unsigned int a = ~(unsigned int)(v & 0xffffffffULL);
        size_t src = (((size_t)b << 17) + a) * 4;
        float d0 = bbox[src + 0] * 0.1f;
        float d1 = bbox[src + 1] * 0.1f;
        float d2 = bbox[src + 2] * 0.2f;
        float d3 = bbox[src + 3] * 0.2f;
        float a0 = anchors[src + 0], a1 = anchors[src + 1];
        float a2 = anchors[src + 2], a3 = anchors[src + 3];
        float h = a2 - a0, w = a3 - a1;
        float cy = a0 + 0.5f * h + d0 * h;
        float cx = a1 + 0.5f * w + d1 * w;
        float h2 = h * expf(d2);
        float w2 = w * expf(d3);
        float y1 = cy - 0.5f * h2;
        float x1 = cx - 0.5f * w2;
        float y2 = y1 + h2;
        float x2 = x1 + w2;
        y1 = fminf(fmaxf(y1, 0.f), 1.f);
        x1 = fminf(fmaxf(x1, 0.f), 1.f);
        y2 = fminf(fmaxf(y2, 0.f), 1.f);
        x2 = fminf(fmaxf(x2, 0.f), 1.f);
        g_boxes[b * NPRE + r] = make_float4(y1, x1, y2, x2);
    }
}

// ---------------- 5a: edge emission over first N1 boxes ----------------
// grid (12 rowblks of 128, 24 colblks of 64, BATCH), 64 threads, 2 rows/thread
__global__ void edge_kernel() {
    int rowblk = blockIdx.x, colblk = blockIdx.y, b = blockIdx.z;
    if (colblk < 2 * rowblk) return;                // tile strictly below diagonal
    int t = threadIdx.x;
    int i0 = rowblk * 128 + t;
    int i1 = i0 + 64;
    __shared__ float4 s_box[64];
    __shared__ float  s_area[64];
    int jj0 = colblk * 64;
    const float4* boxes_b = g_boxes + b * NPRE;
    {
        float4 c = boxes_b[jj0 + t];
        s_box[t] = c;
        s_area[t] = (c.z - c.x) * (c.w - c.y);
    }
    __syncthreads();
    float4 rb0 = boxes_b[i0];
    float4 rb1 = boxes_b[i1];
    float ar0 = (rb0.z - rb0.x) * (rb0.w - rb0.y);
    float ar1 = (rb1.z - rb1.x) * (rb1.w - rb1.y);
#pragma unroll 4
    for (int j = 0; j < 64; ++j) {
        float4 c = s_box[j];
        float ca = s_area[j];
        int jj = jj0 + j;
        float dy0 = fminf(rb0.z, c.z) - fmaxf(rb0.x, c.x);
        float dx0 = fminf(rb0.w, c.w) - fmaxf(rb0.y, c.y);
        float dy1 = fminf(rb1.z, c.z) - fmaxf(rb1.x, c.x);
        float dx1 = fminf(rb1.w, c.w) - fmaxf(rb1.y, c.y);
        bool ov0 = (dy0 > 0.f) && (dx0 > 0.f) && (jj > i0);
        bool ov1 = (dy1 > 0.f) && (dx1 > 0.f) && (jj > i1);
        if (__any_sync(0xffffffffu, ov0 || ov1)) {
            if (ov0) {
                float inter = dy0 * dx0;
                float uni = fmaxf(ar0 + ca - inter, 1e-12f);
                if (__fdiv_rn(inter, uni) > NMS_THR) {
                    int pos = atomicAdd(&g_ecnt[b], 1);
                    if (pos < ECAP)
                        g_edges[b * ECAP + pos] = ((unsigned int)i0 << 16) | (unsigned int)jj;
                }
            }
            if (ov1) {
                float inter = dy1 * dx1;
                float uni = fmaxf(ar1 + ca - inter, 1e-12f);
                if (__fdiv_rn(inter, uni) > NMS_THR) {
                    int pos = atomicAdd(&g_ecnt[b], 1);
                    if (pos < ECAP)
                        g_edges[b * ECAP + pos] = ((unsigned int)i1 << 16) | (unsigned int)jj;
                }
            }
        }
    }
}

// ---------------- 6a: sparse fixpoint NMS on prefix (1 block / batch) ----------------
__global__ void fixpoint_kernel() {
    int b = blockIdx.x, t = threadIdx.x;            // 256 threads
    __shared__ unsigned int  s_edges[ECAP];
    __shared__ unsigned char s_keep[N1];
    __shared__ unsigned char s_supp[N1];
    __shared__ int s_changed;
    __shared__ int s_total;
    int ec = g_ecnt[b];
    if (ec > ECAP) { if (t == 0) g_done[b] = 0; return; }
    for (int i = t; i < ec; i += 256) s_edges[i] = g_edges[b * ECAP + i];
    for (int i = t; i < N1; i += 256) s_keep[i] = 1;
    __syncthreads();
    bool converged = false;
    for (int pass = 0; pass < PASSMAX; ++pass) {
        for (int i = t; i < N1; i += 256) s_supp[i] = 0;
        if (t == 0) s_changed = 0;
        __syncthreads();
        for (int e = t; e < ec; e += 256) {
            unsigned int p = s_edges[e];
            if (s_keep[p >> 16]) s_supp[p & 0xffffu] = 1;
        }
        __syncthreads();
        int ch = 0;
        for (int i = t; i < N1; i += 256) {
            unsigned char nk = (unsigned char)(1 - s_supp[i]);
            if (nk != s_keep[i]) { s_keep[i] = nk; ch = 1; }
        }
        if (ch) s_changed = 1;
        __syncthreads();
        if (!s_changed) { converged = true; break; }
    }
    // count kept + write out
    if (t == 0) s_total = 0;
    __syncthreads();
    int cnt = 0;
    for (int i = t; i < N1; i += 256) {
        g_keep[b * NPRE + i] = s_keep[i];
        cnt += s_keep[i];
    }
    // warp + block reduce
    for (int off = 16; off > 0; off >>= 1) cnt += __shfl_down_sync(0xffffffffu, cnt, off);
    if ((t & 31) == 0) atomicAdd(&s_total, cnt);
    __syncthreads();
    if (t == 0) g_done[b] = (converged && s_total >= NPROP) ? 1 : 0;
}

// ---------------- 5b: fallback full mask (persistent, guarded) ----------------
#define RB 47
#define CB 94
__global__ void mask_fb_kernel() {
    int t = threadIdx.x;
    const int T = BATCH * RB * CB;
    for (int tile = blockIdx.x; tile < T; tile += gridDim.x) {
        int b = tile / (RB * CB);
        if (g_done[b]) continue;
        int rb_ = (tile / CB) % RB;
        int cb_ = tile % CB;
        int i0 = rb_ * 128 + t;
        int i1 = i0 + 64;
        unsigned long long* mrow = g_mask + (size_t)b * NPRE * NB;
        if (cb_ < 2 * rb_) {
            if (i0 < NPRE) mrow[(size_t)i0 * NB + cb_] = 0ULL;
            if (i1 < NPRE) mrow[(size_t)i1 * NB + cb_] = 0ULL;
            continue;
        }
        __shared__ float4 s_box[64];
        __shared__ float  s_area[64];
        int jj0 = cb_ * 64;
        const float4* boxes_b = g_boxes + b * NPRE;
        {
            int jj = jj0 + t;
            float4 c = (jj < NPRE) ? boxes_b[jj] : make_float4(4.f, 4.f, 3.f, 3.f);
            s_box[t] = c;
            s_area[t] = (c.z - c.x) * (c.w - c.y);
        }
        __syncthreads();
        float4 rb0 = (i0 < NPRE) ? boxes_b[i0] : make_float4(4.f, 4.f, 3.f, 3.f);
        float4 rb1 = (i1 < NPRE) ? boxes_b[i1] : make_float4(4.f, 4.f, 3.f, 3.f);
        float ar0 = (rb0.z - rb0.x) * (rb0.w - rb0.y);
        float ar1 = (rb1.z - rb1.x) * (rb1.w - rb1.y);
        unsigned long long bits0 = 0ULL, bits1 = 0ULL;
#pragma unroll 4
        for (int j = 0; j < 64; ++j) {
            float4 c = s_box[j];
            float ca = s_area[j];
            int jj = jj0 + j;
            float dy0 = fminf(rb0.z, c.z) - fmaxf(rb0.x, c.x);
            float dx0 = fminf(rb0.w, c.w) - fmaxf(rb0.y, c.y);
            float dy1 = fminf(rb1.z, c.z) - fmaxf(rb1.x, c.x);
            float dx1 = fminf(rb1.w, c.w) - fmaxf(rb1.y, c.y);
            bool ov0 = (dy0 > 0.f) && (dx0 > 0.f) && (jj > i0);
            bool ov1 = (dy1 > 0.f) && (dx1 > 0.f) && (jj > i1);
            if (__any_sync(0xffffffffu, ov0 || ov1)) {
                if (ov0) {
                    float inter = dy0 * dx0;
                    float uni = fmaxf(ar0 + ca - inter, 1e-12f);
                    if (__fdiv_rn(inter, uni) > NMS_THR) bits0 |= (1ULL << j);
                }
                if (ov1) {
                    float inter = dy1 * dx1;
                    float uni = fmaxf(ar1 + ca - inter, 1e-12f);
                    if (__fdiv_rn(inter, uni) > NMS_THR) bits1 |= (1ULL << j);
                }
            }
        }
        if (i0 < NPRE) mrow[(size_t)i0 * NB + cb_] = bits0;
        if (i1 < NPRE) mrow[(size_t)i1 * NB + cb_] = bits1;
        __syncthreads();
    }
}

// ---------------- 6b: fallback full scan (guarded) ----------------
__global__ void nms_scan_kernel() {
    int b = blockIdx.x, t = threadIdx.x;            // 32 threads
    if (g_done[b]) return;
    __shared__ unsigned long long ring[16 * 96];
    for (int k = t; k < 16 * 96; k += 32) ring[k] = 0ULL;
    __syncwarp();
    unsigned long long r0 = 0, r1 = 0, r2 = 0;
    unsigned int sbase = (unsigned int)__cvta_generic_to_shared(ring);
    const unsigned long long* mrow = g_mask + (size_t)b * NPRE * NB;
    for (int r = 0; r < 16; ++r) {
        const unsigned long long* src = mrow + (size_t)r * NB;
        unsigned int dst = sbase + (unsigned int)((r * 96 + t) * 8);
        cp_async8(dst, src + t);
        cp_async8(dst + 32 * 8, src + t + 32);
        if (t < 30) cp_async8(dst + 64 * 8, src + t + 64);
        cp_commit();
    }
    for (int i = 0; i < NPRE; ++i) {
        cp_wait15();
        int wi = i >> 6;
        unsigned long long v = (wi < 32) ? r0 : (wi < 64) ? r1 : r2;
        unsigned long long wv = __shfl_sync(0xffffffffu, v, wi & 31);
        int supp = (int)((wv >> (i & 63)) & 1ULL);
        int slot = i & 15;
        if (!supp) {
            r0 |= ring[slot * 96 + t];
            r1 |= ring[slot * 96 + t + 32];
            r2 |= ring[slot * 96 + t + 64];
        }
        if (t == 0) g_keep[b * NPRE + i] = (unsigned char)(supp ^ 1);
        int r = i + 16;
        if (r < NPRE) {
            const unsigned long long* src = mrow + (size_t)r * NB;
            unsigned int dst = sbase + (unsigned int)(((r & 15) * 96 + t) * 8);
            cp_async8(dst, src + t);
            cp_async8(dst + 32 * 8, src + t + 32);
            if (t < 30) cp_async8(dst + 64 * 8, src + t + 64);
        }
        cp_commit();
    }
}

// ---------------- 7: compact kept boxes -> output ----------------
__global__ void final_kernel(float* __restrict__ out) {
    int b = blockIdx.x, t = threadIdx.x;            // 1024 threads
    for (int k = t; k < NPROP * 4; k += blockDim.x) out[b * NPROP * 4 + k] = 0.f;
    __syncthreads();
    __shared__ int sc[1024];
    __shared__ int s_off;
    if (t == 0) s_off = 0;
    __syncthreads();
    for (int tile = 0; tile < 6; ++tile) {
        int i = tile * 1024 + t;
        int kp = (i < NPRE) ? (int)g_keep[b * NPRE + i] : 0;
        sc[t] = kp;
        __syncthreads();
        for (int d = 1; d < 1024; d <<= 1) {
            int v = (t >= d) ? sc[t - d] : 0;
            __syncthreads();
            sc[t] += v;
            __syncthreads();
        }
        int off = s_off;
        if (kp) {
            int rank = off + sc[t] - 1;
            if (rank < NPROP)
                ((float4*)out)[b * NPROP + rank] = g_boxes[b * NPRE + i];
        }
        __syncthreads();
        if (t == 1023) s_off = off + sc[1023];
        __syncthreads();
    }
}

// ---------------- launch ----------------
extern "C" void kernel_launch(void* const* d_in, const int* in_sizes, int n_in,
                              void* d_out, int out_size) {
    const float* probs   = (const float*)d_in[0];
    const float* bbox    = (const float*)d_in[1];
    const float* anchors = (const float*)d_in[2];
    float* out = (float*)d_out;

    zero_kernel<<<128, 1024>>>();
    hist_kernel<<<1024, 256>>>(probs);
    cutoff_kernel<<<BATCH, 1024>>>();
    compact_kernel<<<1024, 256>>>(probs);
    cudaFuncSetAttribute(sort_box_kernel,
                         cudaFuncAttributeMaxDynamicSharedMemorySize, CAND_CAP * 8);
    sort_box_kernel<<<BATCH, 1024, CAND_CAP * 8>>>(bbox, anchors);
    edge_kernel<<<dim3(12, 24, BATCH), 64>>>();
    fixpoint_kernel<<<BATCH, 256>>>();
    mask_fb_kernel<<<296, 64>>>();                  // near no-op when done
    nms_scan_kernel<<<BATCH, 32>>>();               // no-op when done
    final_kernel<<<BATCH, 1024>>>(out);
}

// round 5
// speedup vs baseline: 5.9080x; 1.3185x over previous
#include <cuda_runtime.h>
#include <cstdint>
#include <math.h>

#define BATCH 8
#define NA 131072            // anchors per batch (2^17)
#define NPRE 6000            // PRE_NMS_LIMIT
#define NB 94                // ceil(NPRE/64)  (fallback mask)
#define NPROP 1000
#define CAND_CAP 8192
#define HBINS 16384          // key >> 18
#define NMS_THR 0.7f
#define N1 1536              // phase-1 prefix rows
#define ECAP 6144            // edge list capacity per batch
#define PASSMAX 64

typedef unsigned long long u64;

// ---------------- device scratch (static, no allocation) ----------------
__device__ unsigned int  g_hist[BATCH * HBINS];
__device__ int           g_cutbin[BATCH];
__device__ int           g_cand_cnt[BATCH];
__device__ u64           g_cand[BATCH * CAND_CAP];
__device__ float4        g_boxes[BATCH * NPRE];
__device__ int           g_ecnt[BATCH];
__device__ unsigned int  g_edges[BATCH * ECAP];
__device__ u64           g_mask[(size_t)BATCH * NPRE * NB];
__device__ unsigned char g_keep[BATCH * NPRE];
__device__ int           g_done[BATCH];

// ---------------- helpers ----------------
static __device__ __forceinline__ void cp_async8(unsigned int smem, const void* g) {
    asm volatile("cp.async.ca.shared.global [%0], [%1], 8;" :: "r"(smem), "l"(g) : "memory");
}
static __device__ __forceinline__ void cp_commit() {
    asm volatile("cp.async.commit_group;" ::: "memory");
}
static __device__ __forceinline__ void cp_wait15() {
    asm volatile("cp.async.wait_group 15;" ::: "memory");
}
static __device__ __forceinline__ unsigned int score_key(float s) {
    unsigned int u = __float_as_uint(s);
    return u ^ ((unsigned int)((int)u >> 31) | 0x80000000u);
}

// ---------------- 0: zero scratch ----------------
__global__ void zero_kernel() {
    int gid = blockIdx.x * blockDim.x + threadIdx.x;
    int stride = gridDim.x * blockDim.x;
    for (int i = gid; i < BATCH * HBINS; i += stride) g_hist[i] = 0u;
    if (gid < BATCH * NPRE) g_keep[gid] = 0;
    if (gid < BATCH) { g_cand_cnt[gid] = 0; g_done[gid] = 0; g_ecnt[gid] = 0; }
}

// ---------------- 1: histogram (MLP=8 front-batched loads) ----------------
// 256 blocks x 256 threads; block covers 2048 float4 = 4096 scores, one batch
__global__ void hist_kernel(const float* __restrict__ probs) {
    const float4* p4 = (const float4*)probs;
    int t = threadIdx.x;
    int base = blockIdx.x * 2048;
    int b = base >> 16;                 // 65536 float4 per batch
    float4 x[8];
#pragma unroll
    for (int u = 0; u < 8; ++u) x[u] = p4[base + u * 256 + t];
    unsigned int* Hb = g_hist + (size_t)b * HBINS;
#pragma unroll
    for (int u = 0; u < 8; ++u) {
        atomicAdd(&Hb[score_key(x[u].y) >> 18], 1u);
        atomicAdd(&Hb[score_key(x[u].w) >> 18], 1u);
    }
}

// ---------------- 2: cutoff bin via shfl suffix scans ----------------
__global__ void cutoff_kernel() {
    int b = blockIdx.x, t = threadIdx.x;            // 1024 threads, 16 bins each
    __shared__ unsigned int wtot[32];
    __shared__ unsigned int wsuf[32];
    const uint4* H4 = (const uint4*)(g_hist + (size_t)b * HBINS);
    int warp = t >> 5, lane = t & 31;
    uint4 h[4];
#pragma unroll
    for (int u = 0; u < 4; ++u) h[u] = H4[t * 4 + u];
    unsigned int s = 0;
#pragma unroll
    for (int u = 0; u < 4; ++u) s += h[u].x + h[u].y + h[u].z + h[u].w;
    // warp inclusive suffix scan
    unsigned int ss = s;
#pragma unroll
    for (int o = 1; o < 32; o <<= 1) {
        unsigned int v = __shfl_down_sync(0xffffffffu, ss, o);
        if (lane + o < 32) ss += v;
    }
    if (lane == 0) wtot[warp] = ss;                 // warp total
    __syncthreads();
    if (warp == 0) {
        unsigned int wv = wtot[lane];
#pragma unroll
        for (int o = 1; o < 32; o <<= 1) {
            unsigned int v = __shfl_down_sync(0xffffffffu, wv, o);
            if (lane + o < 32) wv += v;
        }
        wsuf[lane] = wv;                            // inclusive suffix of warp totals
    }
    __syncthreads();
    unsigned int after_warp = (warp < 31) ? wsuf[warp + 1] : 0u;
    unsigned int S = ss + after_warp;               // suffix from bin t*16
    unsigned int Snext = S - s;                     // suffix from bin (t+1)*16
    if (S >= NPRE && Snext < NPRE) {
        unsigned int bins[16];
#pragma unroll
        for (int u = 0; u < 4; ++u) {
            bins[u * 4 + 0] = h[u].x; bins[u * 4 + 1] = h[u].y;
            bins[u * 4 + 2] = h[u].z; bins[u * 4 + 3] = h[u].w;
        }
        unsigned int run = Snext;
        int cut = t * 16;
        for (int k = 15; k >= 0; --k) {
            run += bins[k];
            if (run >= NPRE) { cut = t * 16 + k; break; }
        }
        g_cutbin[b] = cut;
    }
}

// ---------------- 3: compact candidates (MLP=8) ----------------
__global__ void compact_kernel(const float* __restrict__ probs) {
    const float4* p4 = (const float4*)probs;
    int t = threadIdx.x;
    int base = blockIdx.x * 2048;
    int b = base >> 16;
    int cut = g_cutbin[b];
    float4 x[8];
#pragma unroll
    for (int u = 0; u < 8; ++u) x[u] = p4[base + u * 256 + t];
#pragma unroll
    for (int u = 0; u < 8; ++u) {
        int j = base + u * 256 + t;                 // float4 index: pairs 2j, 2j+1
        unsigned int k0 = score_key(x[u].y);
        unsigned int k1 = score_key(x[u].w);
        if ((int)(k0 >> 18) >= cut) {
            int pos = atomicAdd(&g_cand_cnt[b], 1);
            if (pos < CAND_CAP) {
                unsigned int a = (unsigned int)((2 * j) & (NA - 1));
                g_cand[b * CAND_CAP + pos] = ((u64)k0 << 32) | (u64)(~a);
            }
        }
        if ((int)(k1 >> 18) >= cut) {
            int pos = atomicAdd(&g_cand_cnt[b], 1);
            if (pos < CAND_CAP) {
                unsigned int a = (unsigned int)((2 * j + 1) & (NA - 1));
                g_cand[b * CAND_CAP + pos] = ((u64)k1 << 32) | (u64)(~a);
            }
        }
    }
}

// ---------------- 4: hybrid register/warp/smem bitonic sort (desc) + decode ----------------
// 1024 threads, 8 elems/thread in registers; thread t owns elements [8t, 8t+8)
static __device__ __forceinline__ void shfl_stage(u64 v[8], int t, int j, int k) {
    int jm = j >> 3;
#pragma unroll
    for (int r = 0; r < 8; ++r) {
        u64 other = __shfl_xor_sync(0xffffffffu, v[r], jm);
        int i = t * 8 + r;
        bool lower = (t & jm) == 0;
        bool desc = ((i & k) == 0);
        bool take_max = (lower == desc);
        u64 mx = v[r] > other ? v[r] : other;
        u64 mn = v[r] > other ? other : v[r];
        v[r] = take_max ? mx : mn;
    }
}
static __device__ __forceinline__ void reg_stage(u64 v[8], int t, int j, int k) {
#pragma unroll
    for (int a = 0; a < 8; ++a) {
        if (!(a & j)) {
            int i = t * 8 + a;
            bool desc = ((i & k) == 0);
            u64 x = v[a], y = v[a + j];
            if (desc ? (x < y) : (x > y)) { v[a] = y; v[a + j] = x; }
        }
    }
}

__global__ void sort_box_kernel(const float* __restrict__ bbox,
                                const float* __restrict__ anchors) {
    __shared__ u64 sh[CAND_CAP];
    int b = blockIdx.x, t = threadIdx.x;            // 1024 threads
    int cnt = g_cand_cnt[b]; if (cnt > CAND_CAP) cnt = CAND_CAP;
    const u64* src = g_cand + b * CAND_CAP;
    u64 v[8];
#pragma unroll
    for (int r = 0; r < 8; ++r) {
        int i = t * 8 + r;
        v[r] = (i < cnt) ? src[i] : 0ULL;
    }
    // phase A: k = 2..256 entirely in registers / warp shuffles
    for (int k = 2; k <= 256; k <<= 1) {
        for (int j = k >> 1; j >= 8; j >>= 1) shfl_stage(v, t, j, k);
        if (k > 4) reg_stage(v, t, 4, k);
        if (k > 2) reg_stage(v, t, 2, k);
        reg_stage(v, t, 1, k);
    }
    // phase B: k = 512..8192 — j>=256 via smem, rest in registers
    for (int k = 512; k <= CAND_CAP; k <<= 1) {
#pragma unroll
        for (int r = 0; r < 8; ++r) sh[t * 8 + r] = v[r];
        __syncthreads();
        for (int j = k >> 1; j >= 256; j >>= 1) {
#pragma unroll
            for (int w = 0; w < 8; ++w) {
                int i = w * 1024 + t;
                int l = i ^ j;
                if (l > i) {
                    u64 x = sh[i], y = sh[l];
                    bool desc = ((i & k) == 0);
                    if (desc ? (x < y) : (x > y)) { sh[i] = y; sh[l] = x; }
                }
            }
            __syncthreads();
        }
#pragma unroll
        for (int r = 0; r < 8; ++r) v[r] = sh[t * 8 + r];
        for (int j = 128; j >= 8; j >>= 1) shfl_stage(v, t, j, k);
        reg_stage(v, t, 4, k);
        reg_stage(v, t, 2, k);
        reg_stage(v, t, 1, k);
    }
    // decode: thread t owns ranks 8t..8t+7 (sorted desc)
#pragma unroll
    for (int r = 0; r < 8; ++r) {
        int rank = t * 8 + r;
        if (rank < NPRE) {
            unsigned int a = ~(unsigned int)(v[r] & 0xffffffffULL);
            size_t s4 = (((size_t)b << 17) + a) * 4;
            float d0 = bbox[s4 + 0] * 0.1f;
            float d1 = bbox[s4 + 1] * 0.1f;
            float d2 = bbox[s4 + 2] * 0.2f;
            float d3 = bbox[s4 + 3] * 0.2f;
            float a0 = anchors[s4 + 0], a1 = anchors[s4 + 1];
            float a2 = anchors[s4 + 2], a3 = anchors[s4 + 3];
            float h = a2 - a0, w = a3 - a1;
            float cy = a0 + 0.5f * h + d0 * h;
            float cx = a1 + 0.5f * w + d1 * w;
            float h2 = h * expf(d2);
            float w2 = w * expf(d3);
            float y1 = cy - 0.5f * h2;
            float x1 = cx - 0.5f * w2;
            float y2 = y1 + h2;
            float x2 = x1 + w2;
            y1 = fminf(fmaxf(y1, 0.f), 1.f);
            x1 = fminf(fmaxf(x1, 0.f), 1.f);
            y2 = fminf(fmaxf(y2, 0.f), 1.f);
            x2 = fminf(fmaxf(x2, 0.f), 1.f);
            g_boxes[b * NPRE + rank] = make_float4(y1, x1, y2, x2);
        }
    }
}

// ---------------- 5a: edge emission over first N1 boxes ----------------
__global__ void edge_kernel() {
    int rowblk = blockIdx.x, colblk = blockIdx.y, b = blockIdx.z;
    if (colblk < 2 * rowblk) return;
    int t = threadIdx.x;
    int i0 = rowblk * 128 + t;
    int i1 = i0 + 64;
    __shared__ float4 s_box[64];
    __shared__ float  s_area[64];
    int jj0 = colblk * 64;
    const float4* boxes_b = g_boxes + b * NPRE;
    {
        float4 c = boxes_b[jj0 + t];
        s_box[t] = c;
        s_area[t] = (c.z - c.x) * (c.w - c.y);
    }
    __syncthreads();
    float4 rb0 = boxes_b[i0];
    float4 rb1 = boxes_b[i1];
    float ar0 = (rb0.z - rb0.x) * (rb0.w - rb0.y);
    float ar1 = (rb1.z - rb1.x) * (rb1.w - rb1.y);
#pragma unroll 4
    for (int j = 0; j < 64; ++j) {
        float4 c = s_box[j];
        float ca = s_area[j];
        int jj = jj0 + j;
        float dy0 = fminf(rb0.z, c.z) - fmaxf(rb0.x, c.x);
        float dx0 = fminf(rb0.w, c.w) - fmaxf(rb0.y, c.y);
        float dy1 = fminf(rb1.z, c.z) - fmaxf(rb1.x, c.x);
        float dx1 = fminf(rb1.w, c.w) - fmaxf(rb1.y, c.y);
        bool ov0 = (dy0 > 0.f) && (dx0 > 0.f) && (jj > i0);
        bool ov1 = (dy1 > 0.f) && (dx1 > 0.f) && (jj > i1);
        if (__any_sync(0xffffffffu, ov0 || ov1)) {
            if (ov0) {
                float inter = dy0 * dx0;
                float uni = fmaxf(ar0 + ca - inter, 1e-12f);
                if (__fdiv_rn(inter, uni) > NMS_THR) {
                    int pos = atomicAdd(&g_ecnt[b], 1);
                    if (pos < ECAP)
                        g_edges[b * ECAP + pos] = ((unsigned int)i0 << 16) | (unsigned int)jj;
                }
            }
            if (ov1) {
                float inter = dy1 * dx1;
                float uni = fmaxf(ar1 + ca - inter, 1e-12f);
                if (__fdiv_rn(inter, uni) > NMS_THR) {
                    int pos = atomicAdd(&g_ecnt[b], 1);
                    if (pos < ECAP)
                        g_edges[b * ECAP + pos] = ((unsigned int)i1 << 16) | (unsigned int)jj;
                }
            }
        }
    }
}

// ---------------- 6a: sparse fixpoint NMS on prefix (1 block / batch) ----------------
__global__ void fixpoint_kernel() {
    int b = blockIdx.x, t = threadIdx.x;            // 256 threads
    __shared__ unsigned int  s_edges[ECAP];
    __shared__ unsigned char s_keep[N1];
    __shared__ unsigned char s_supp[N1];
    __shared__ int s_changed;
    __shared__ int s_total;
    int ec = g_ecnt[b];
    if (ec > ECAP) { if (t == 0) g_done[b] = 0; return; }
    for (int i = t; i < ec; i += 256) s_edges[i] = g_edges[b * ECAP + i];
    for (int i = t; i < N1; i += 256) s_keep[i] = 1;
    __syncthreads();
    bool converged = false;
    for (int pass = 0; pass < PASSMAX; ++pass) {
        for (int i = t; i < N1; i += 256) s_supp[i] = 0;
        if (t == 0) s_changed = 0;
        __syncthreads();
        for (int e = t; e < ec; e += 256) {
            unsigned int p = s_edges[e];
            if (s_keep[p >> 16]) s_supp[p & 0xffffu] = 1;
        }
        __syncthreads();
        int ch = 0;
        for (int i = t; i < N1; i += 256) {
            unsigned char nk = (unsigned char)(1 - s_supp[i]);
            if (nk != s_keep[i]) { s_keep[i] = nk; ch = 1; }
        }
        if (ch) s_changed = 1;
        __syncthreads();
        if (!s_changed) { converged = true; break; }
    }
    if (t == 0) s_total = 0;
    __syncthreads();
    int cnt = 0;
    for (int i = t; i < N1; i += 256) {
        g_keep[b * NPRE + i] = s_keep[i];
        cnt += s_keep[i];
    }
    for (int off = 16; off > 0; off >>= 1) cnt += __shfl_down_sync(0xffffffffu, cnt, off);
    if ((t & 31) == 0) atomicAdd(&s_total, cnt);
    __syncthreads();
    if (t == 0) g_done[b] = (converged && s_total >= NPROP) ? 1 : 0;
}

// ---------------- 5b: fallback full mask (persistent, guarded) ----------------
#define RB 47
#define CB 94
__global__ void mask_fb_kernel() {
    int t = threadIdx.x;
    const int T = BATCH * RB * CB;
    for (int tile = blockIdx.x; tile < T; tile += gridDim.x) {
        int b = tile / (RB * CB);
        if (g_done[b]) continue;
        int rb_ = (tile / CB) % RB;
        int cb_ = tile % CB;
        int i0 = rb_ * 128 + t;
        int i1 = i0 + 64;
        u64* mrow = g_mask + (size_t)b * NPRE * NB;
        if (cb_ < 2 * rb_) {
            if (i0 < NPRE) mrow[(size_t)i0 * NB + cb_] = 0ULL;
            if (i1 < NPRE) mrow[(size_t)i1 * NB + cb_] = 0ULL;
            continue;
        }
        __shared__ float4 s_box[64];
        __shared__ float  s_area[64];
        int jj0 = cb_ * 64;
        const float4* boxes_b = g_boxes + b * NPRE;
        {
            int jj = jj0 + t;
            float4 c = (jj < NPRE) ? boxes_b[jj] : make_float4(4.f, 4.f, 3.f, 3.f);
            s_box[t] = c;
            s_area[t] = (c.z - c.x) * (c.w - c.y);
        }
        __syncthreads();
        float4 rb0 = (i0 < NPRE) ? boxes_b[i0] : make_float4(4.f, 4.f, 3.f, 3.f);
        float4 rb1 = (i1 < NPRE) ? boxes_b[i1] : make_float4(4.f, 4.f, 3.f, 3.f);
        float ar0 = (rb0.z - rb0.x) * (rb0.w - rb0.y);
        float ar1 = (rb1.z - rb1.x) * (rb1.w - rb1.y);
        u64 bits0 = 0ULL, bits1 = 0ULL;
#pragma unroll 4
        for (int j = 0; j < 64; ++j) {
            float4 c = s_box[j];
            float ca = s_area[j];
            int jj = jj0 + j;
            float dy0 = fminf(rb0.z, c.z) - fmaxf(rb0.x, c.x);
            float dx0 = fminf(rb0.w, c.w) - fmaxf(rb0.y, c.y);
            float dy1 = fminf(rb1.z, c.z) - fmaxf(rb1.x, c.x);
            float dx1 = fminf(rb1.w, c.w) - fmaxf(rb1.y, c.y);
            bool ov0 = (dy0 > 0.f) && (dx0 > 0.f) && (jj > i0);
            bool ov1 = (dy1 > 0.f) && (dx1 > 0.f) && (jj > i1);
            if (__any_sync(0xffffffffu, ov0 || ov1)) {
                if (ov0) {
                    float inter = dy0 * dx0;
                    float uni = fmaxf(ar0 + ca - inter, 1e-12f);
                    if (__fdiv_rn(inter, uni) > NMS_THR) bits0 |= (1ULL << j);
                }
                if (ov1) {
                    float inter = dy1 * dx1;
                    float uni = fmaxf(ar1 + ca - inter, 1e-12f);
                    if (__fdiv_rn(inter, uni) > NMS_THR) bits1 |= (1ULL << j);
                }
            }
        }
        if (i0 < NPRE) mrow[(size_t)i0 * NB + cb_] = bits0;
        if (i1 < NPRE) mrow[(size_t)i1 * NB + cb_] = bits1;
        __syncthreads();
    }
}

// ---------------- 6b: fallback full scan (guarded) ----------------
__global__ void nms_scan_kernel() {
    int b = blockIdx.x, t = threadIdx.x;            // 32 threads
    if (g_done[b]) return;
    __shared__ u64 ring[16 * 96];
    for (int k = t; k < 16 * 96; k += 32) ring[k] = 0ULL;
    __syncwarp();
    u64 r0 = 0, r1 = 0, r2 = 0;
    unsigned int sbase = (unsigned int)__cvta_generic_to_shared(ring);
    const u64* mrow = g_mask + (size_t)b * NPRE * NB;
    for (int r = 0; r < 16; ++r) {
        const u64* src = mrow + (size_t)r * NB;
        unsigned int dst = sbase + (unsigned int)((r * 96 + t) * 8);
        cp_async8(dst, src + t);
        cp_async8(dst + 32 * 8, src + t + 32);
        if (t < 30) cp_async8(dst + 64 * 8, src + t + 64);
        cp_commit();
    }
    for (int i = 0; i < NPRE; ++i) {
        cp_wait15();
        int wi = i >> 6;
        u64 v = (wi < 32) ? r0 : (wi < 64) ? r1 : r2;
        u64 wv = __shfl_sync(0xffffffffu, v, wi & 31);
        int supp = (int)((wv >> (i & 63)) & 1ULL);
        int slot = i & 15;
        if (!supp) {
            r0 |= ring[slot * 96 + t];
            r1 |= ring[slot * 96 + t + 32];
            r2 |= ring[slot * 96 + t + 64];
        }
        if (t == 0) g_keep[b * NPRE + i] = (unsigned char)(supp ^ 1);
        int r = i + 16;
        if (r < NPRE) {
            const u64* src = mrow + (size_t)r * NB;
            unsigned int dst = sbase + (unsigned int)(((r & 15) * 96 + t) * 8);
            cp_async8(dst, src + t);
            cp_async8(dst + 32 * 8, src + t + 32);
            if (t < 30) cp_async8(dst + 64 * 8, src + t + 64);
        }
        cp_commit();
    }
}

// ---------------- 7: compact kept boxes -> output (ballot scan) ----------------
__global__ void final_kernel(float* __restrict__ out) {
    int b = blockIdx.x, t = threadIdx.x;            // 1024 threads
    for (int k = t; k < NPROP * 4; k += 1024) out[b * NPROP * 4 + k] = 0.f;
    __shared__ int wsum[32];
    __shared__ int s_base;
    if (t == 0) s_base = 0;
    int warp = t >> 5, lane = t & 31;
    __syncthreads();
    for (int tile = 0; tile < 6; ++tile) {
        int i = tile * 1024 + t;
        int kp = (i < NPRE) ? (int)g_keep[b * NPRE + i] : 0;
        unsigned int m = __ballot_sync(0xffffffffu, kp);
        if (lane == 0) wsum[warp] = __popc(m);
        __syncthreads();
        int base = s_base;
        if (warp == 0) {
            int wv = wsum[lane];
#pragma unroll
            for (int o = 1; o < 32; o <<= 1) {
                int u = __shfl_up_sync(0xffffffffu, wv, o);
                if (lane >= o) wv += u;
            }
            wsum[lane] = wv;                        // inclusive
        }
        __syncthreads();
        int prev = (warp == 0) ? 0 : wsum[warp - 1];
        int rank = base + prev + __popc(m & ((1u << lane) - 1u));
        if (kp && rank < NPROP)
            ((float4*)out)[b * NPROP + rank] = g_boxes[b * NPRE + i];
        __syncthreads();
        if (t == 0) s_base = base + wsum[31];
        __syncthreads();
    }
}

// ---------------- launch ----------------
extern "C" void kernel_launch(void* const* d_in, const int* in_sizes, int n_in,
                              void* d_out, int out_size) {
    const float* probs   = (const float*)d_in[0];
    const float* bbox    = (const float*)d_in[1];
    const float* anchors = (const float*)d_in[2];
    float* out = (float*)d_out;

    zero_kernel<<<128, 1024>>>();
    hist_kernel<<<256, 256>>>(probs);
    cutoff_kernel<<<BATCH, 1024>>>();
    compact_kernel<<<256, 256>>>(probs);
    sort_box_kernel<<<BATCH, 1024>>>(bbox, anchors);
    edge_kernel<<<dim3(12, 24, BATCH), 64>>>();
    fixpoint_kernel<<<BATCH, 256>>>();
    mask_fb_kernel<<<296, 64>>>();                  // near no-op when done
    nms_scan_kernel<<<BATCH, 32>>>();               // no-op when done
    final_kernel<<<BATCH, 1024>>>(out);
}

// round 7
// speedup vs baseline: 6.4924x; 1.0989x over previous
#include <cuda_runtime.h>
#include <cstdint>
#include <math.h>

#define BATCH 8
#define NA 131072            // anchors per batch (2^17)
#define NPRE 6000            // PRE_NMS_LIMIT
#define NB 94                // ceil(NPRE/64)  (fallback mask)
#define NPROP 1000
#define CAND_CAP 8192
#define HBINS 16384          // key >> 18
#define NMS_THR 0.7f
#define N1 1536              // phase-1 prefix rows
#define ECAP 6144            // edge list capacity per batch
#define PASSMAX 64

typedef unsigned long long u64;

// ---------------- device scratch (static, no allocation) ----------------
// Invariants: g_hist is all-zero and g_cand_cnt/g_ecnt are zero at entry of each
// kernel_launch call (zero-init at load; each consumer kernel re-zeroes after use).
__device__ unsigned int  g_hist[BATCH * HBINS];
__device__ int           g_cutbin[BATCH];
__device__ int           g_cand_cnt[BATCH];
__device__ u64           g_cand[BATCH * CAND_CAP];
__device__ float4        g_boxes[BATCH * NPRE];
__device__ int           g_ecnt[BATCH];
__device__ unsigned int  g_edges[BATCH * ECAP];
__device__ u64           g_mask[(size_t)BATCH * NPRE * NB];
__device__ unsigned char g_keep[BATCH * NPRE];
__device__ int           g_done[BATCH];

// ---------------- helpers ----------------
static __device__ __forceinline__ void cp_async8(unsigned int smem, const void* g) {
    asm volatile("cp.async.ca.shared.global [%0], [%1], 8;" :: "r"(smem), "l"(g) : "memory");
}
static __device__ __forceinline__ void cp_commit() {
    asm volatile("cp.async.commit_group;" ::: "memory");
}
static __device__ __forceinline__ void cp_wait15() {
    asm volatile("cp.async.wait_group 15;" ::: "memory");
}
static __device__ __forceinline__ unsigned int score_key(float s) {
    unsigned int u = __float_as_uint(s);
    return u ^ ((unsigned int)((int)u >> 31) | 0x80000000u);
}
// warp-aggregated allocation: returns this lane's slot (valid only if pred)
static __device__ __forceinline__ int warp_alloc(bool pred, int* ctr) {
    unsigned int m = __ballot_sync(0xffffffffu, pred);
    int lane = threadIdx.x & 31;
    int leader = __ffs(m) - 1;
    int base = 0;
    if (m) {
        if (lane == leader) base = atomicAdd(ctr, __popc(m));
        base = __shfl_sync(0xffffffffu, base, leader);
    }
    return base + __popc(m & ((1u << lane) - 1u));
}

// ---------------- 1: histogram (512 blocks x 256 thr, 4 float4/thread) ----------------
__global__ void hist_kernel(const float* __restrict__ probs) {
    const float4* p4 = (const float4*)probs;
    int t = threadIdx.x;
    int base = blockIdx.x * 1024;
    int b = base >> 16;                 // 65536 float4 per batch; blocks never straddle
    float4 x[4];
#pragma unroll
    for (int u = 0; u < 4; ++u) x[u] = p4[base + u * 256 + t];
    unsigned int* Hb = g_hist + (size_t)b * HBINS;
#pragma unroll
    for (int u = 0; u < 4; ++u) {
        atomicAdd(&Hb[score_key(x[u].y) >> 18], 1u);
        atomicAdd(&Hb[score_key(x[u].w) >> 18], 1u);
    }
}

// ---------------- 2: cutoff bin via shfl suffix scans (+ self-clean hist) ----------------
__global__ void cutoff_kernel() {
    int b = blockIdx.x, t = threadIdx.x;            // 1024 threads, 16 bins each
    __shared__ unsigned int wtot[32];
    __shared__ unsigned int wsuf[32];
    uint4* H4 = (uint4*)(g_hist + (size_t)b * HBINS);
    int warp = t >> 5, lane = t & 31;
    uint4 h[4];
#pragma unroll
    for (int u = 0; u < 4; ++u) h[u] = H4[t * 4 + u];
    // self-clean: restore the all-zero invariant for the next call
    uint4 z = make_uint4(0u, 0u, 0u, 0u);
#pragma unroll
    for (int u = 0; u < 4; ++u) H4[t * 4 + u] = z;
    unsigned int s = 0;
#pragma unroll
    for (int u = 0; u < 4; ++u) s += h[u].x + h[u].y + h[u].z + h[u].w;
    unsigned int ss = s;
#pragma unroll
    for (int o = 1; o < 32; o <<= 1) {
        unsigned int v = __shfl_down_sync(0xffffffffu, ss, o);
        if (lane + o < 32) ss += v;
    }
    if (lane == 0) wtot[warp] = ss;
    __syncthreads();
    if (warp == 0) {
        unsigned int wv = wtot[lane];
#pragma unroll
        for (int o = 1; o < 32; o <<= 1) {
            unsigned int v = __shfl_down_sync(0xffffffffu, wv, o);
            if (lane + o < 32) wv += v;
        }
        wsuf[lane] = wv;
    }
    __syncthreads();
    unsigned int after_warp = (warp < 31) ? wsuf[warp + 1] : 0u;
    unsigned int S = ss + after_warp;
    unsigned int Snext = S - s;
    if (S >= NPRE && Snext < NPRE) {
        unsigned int bins[16];
#pragma unroll
        for (int u = 0; u < 4; ++u) {
            bins[u * 4 + 0] = h[u].x; bins[u * 4 + 1] = h[u].y;
            bins[u * 4 + 2] = h[u].z; bins[u * 4 + 3] = h[u].w;
        }
        unsigned int run = Snext;
        int cut = t * 16;
        for (int k = 15; k >= 0; --k) {
            run += bins[k];
            if (run >= NPRE) { cut = t * 16 + k; break; }
        }
        g_cutbin[b] = cut;
    }
}

// ---------------- 3: compact candidates (512 blocks, warp-aggregated alloc) ----------------
__global__ void compact_kernel(const float* __restrict__ probs) {
    const float4* p4 = (const float4*)probs;
    int t = threadIdx.x;
    int base = blockIdx.x * 1024;
    int b = base >> 16;
    int cut = g_cutbin[b];
    float4 x[4];
#pragma unroll
    for (int u = 0; u < 4; ++u) x[u] = p4[base + u * 256 + t];
#pragma unroll
    for (int u = 0; u < 4; ++u) {
        int j = base + u * 256 + t;                 // float4 idx: score pairs 2j, 2j+1
        unsigned int k0 = score_key(x[u].y);
        unsigned int k1 = score_key(x[u].w);
        bool p0 = (int)(k0 >> 18) >= cut;
        bool p1 = (int)(k1 >> 18) >= cut;
        int pos0 = warp_alloc(p0, &g_cand_cnt[b]);
        if (p0 && pos0 < CAND_CAP) {
            unsigned int a = (unsigned int)((2 * j) & (NA - 1));
            g_cand[b * CAND_CAP + pos0] = ((u64)k0 << 32) | (u64)(~a);
        }
        int pos1 = warp_alloc(p1, &g_cand_cnt[b]);
        if (p1 && pos1 < CAND_CAP) {
            unsigned int a = (unsigned int)((2 * j + 1) & (NA - 1));
            g_cand[b * CAND_CAP + pos1] = ((u64)k1 << 32) | (u64)(~a);
        }
    }
}

// ---------------- bitonic building blocks ----------------
static __device__ __forceinline__ void shfl_stage(u64 v[8], int t, int j, int k) {
    int jm = j >> 3;                                // partner thread xor (jm <= 16 here)
#pragma unroll
    for (int r = 0; r < 8; ++r) {
        u64 other = __shfl_xor_sync(0xffffffffu, v[r], jm);
        int i = t * 8 + r;
        bool lower = (t & jm) == 0;
        bool desc = ((i & k) == 0);
        bool take_max = (lower == desc);
        u64 mx = v[r] > other ? v[r] : other;
        u64 mn = v[r] > other ? other : v[r];
        v[r] = take_max ? mx : mn;
    }
}
static __device__ __forceinline__ void reg_stage(u64 v[8], int t, int j, int k) {
#pragma unroll
    for (int a = 0; a < 8; ++a) {
        if (!(a & j)) {
            int i = t * 8 + a;
            bool desc = ((i & k) == 0);
            u64 x = v[a], y = v[a + j];
            if (desc ? (x < y) : (x > y)) { v[a] = y; v[a + j] = x; }
        }
    }
}

// ---------------- 4a: local sort of 2048-runs (32 blocks = 4/batch, 256 thr) ----------------
__global__ void local_sort_kernel() {
    __shared__ u64 sh[2048];
    int blk = blockIdx.x, t = threadIdx.x;
    int b = blk >> 2, chunk = blk & 3;
    int cnt = g_cand_cnt[b]; if (cnt > CAND_CAP) cnt = CAND_CAP;
    u64* run = g_cand + b * CAND_CAP + chunk * 2048;
    int valid = cnt - chunk * 2048;                 // may be <=0
    u64 v[8];
#pragma unroll
    for (int r = 0; r < 8; ++r) {
        int i = t * 8 + r;
        v[r] = (i < valid) ? run[i] : 0ULL;
    }
    // k = 2..256: registers + shuffles (warp spans 256 elements)
    for (int k = 2; k <= 256; k <<= 1) {
        for (int j = k >> 1; j >= 8; j >>= 1) shfl_stage(v, t, j, k);
        if (k > 4) reg_stage(v, t, 4, k);
        if (k > 2) reg_stage(v, t, 2, k);
        reg_stage(v, t, 1, k);
    }
    // k = 512..2048: j>=256 via smem
    for (int k = 512; k <= 2048; k <<= 1) {
#pragma unroll
        for (int r = 0; r < 8; ++r) sh[t * 8 + r] = v[r];
        __syncthreads();
        for (int j = k >> 1; j >= 256; j >>= 1) {
#pragma unroll
            for (int w = 0; w < 8; ++w) {
                int i = w * 256 + t;
                int l = i ^ j;
                if (l > i) {
                    u64 x = sh[i], y = sh[l];
                    bool desc = ((i & k) == 0);
                    if (desc ? (x < y) : (x > y)) { sh[i] = y; sh[l] = x; }
                }
            }
            __syncthreads();
        }
#pragma unroll
        for (int r = 0; r < 8; ++r) v[r] = sh[t * 8 + r];
        for (int j = 128; j >= 8; j >>= 1) shfl_stage(v, t, j, k);
        reg_stage(v, t, 4, k);
        reg_stage(v, t, 2, k);
        reg_stage(v, t, 1, k);
    }
#pragma unroll
    for (int r = 0; r < 8; ++r) run[t * 8 + r] = v[r];  // descending run
}

// ---------------- 4b: merge 4 runs + decode (8 blocks, 1024 thr) ----------------
__global__ void merge_decode_kernel(const float* __restrict__ bbox,
                                    const float* __restrict__ anchors) {
    __shared__ u64 sh[CAND_CAP];
    int b = blockIdx.x, t = threadIdx.x;
    const u64* src = g_cand + b * CAND_CAP;
    u64 v[8];
    // load; reverse odd chunks so 2048-blocks alternate desc/asc (bitonic invariant)
#pragma unroll
    for (int r = 0; r < 8; ++r) {
        int g = t * 8 + r;
        int chunk = g >> 11, within = g & 2047;
        int si = (chunk & 1) ? ((chunk << 11) | (2047 - within)) : g;
        v[r] = src[si];
    }
    // k = 4096, 8192 phases complete the sort (descending)
    for (int k = 4096; k <= CAND_CAP; k <<= 1) {
#pragma unroll
        for (int r = 0; r < 8; ++r) sh[t * 8 + r] = v[r];
        __syncthreads();
        for (int j = k >> 1; j >= 256; j >>= 1) {
#pragma unroll
            for (int w = 0; w < 8; ++w) {
                int i = w * 1024 + t;
                int l = i ^ j;
                if (l > i) {
                    u64 x = sh[i], y = sh[l];
                    bool desc = ((i & k) == 0);
                    if (desc ? (x < y) : (x > y)) { sh[i] = y; sh[l] = x; }
                }
            }
            __syncthreads();
        }
#pragma unroll
        for (int r = 0; r < 8; ++r) v[r] = sh[t * 8 + r];
        for (int j = 128; j >= 8; j >>= 1) shfl_stage(v, t, j, k);
        reg_stage(v, t, 4, k);
        reg_stage(v, t, 2, k);
        reg_stage(v, t, 1, k);
    }
    if (t == 0) g_cand_cnt[b] = 0;                  // restore invariant
    // decode ranks 8t..8t+7
#pragma unroll
    for (int r = 0; r < 8; ++r) {
        int rank = t * 8 + r;
        if (rank < NPRE) {
            unsigned int a = ~(unsigned int)(v[r] & 0xffffffffULL);
            size_t s4 = (((size_t)b << 17) + a) * 4;
            float d0 = bbox[s4 + 0] * 0.1f;
            float d1 = bbox[s4 + 1] * 0.1f;
            float d2 = bbox[s4 + 2] * 0.2f;
            float d3 = bbox[s4 + 3] * 0.2f;
            float a0 = anchors[s4 + 0], a1 = anchors[s4 + 1];
            float a2 = anchors[s4 + 2], a3 = anchors[s4 + 3];
            float h = a2 - a0, w = a3 - a1;
            float cy = a0 + 0.5f * h + d0 * h;
            float cx = a1 + 0.5f * w + d1 * w;
            float h2 = h * expf(d2);
            float w2 = w * expf(d3);
            float y1 = cy - 0.5f * h2;
            float x1 = cx - 0.5f * w2;
            float y2 = y1 + h2;
            float x2 = x1 + w2;
            y1 = fminf(fmaxf(y1, 0.f), 1.f);
            x1 = fminf(fmaxf(x1, 0.f), 1.f);
            y2 = fminf(fmaxf(y2, 0.f), 1.f);
            x2 = fminf(fmaxf(x2, 0.f), 1.f);
            g_boxes[b * NPRE + rank] = make_float4(y1, x1, y2, x2);
        }
    }
}

// ---------------- 5a: edge emission over first N1 boxes ----------------
__global__ void edge_kernel() {
    int rowblk = blockIdx.x, colblk = blockIdx.y, b = blockIdx.z;
    if (colblk < 2 * rowblk) return;
    int t = threadIdx.x;
    int i0 = rowblk * 128 + t;
    int i1 = i0 + 64;
    __shared__ float4 s_box[64];
    __shared__ float  s_area[64];
    int jj0 = colblk * 64;
    const float4* boxes_b = g_boxes + b * NPRE;
    {
        float4 c = boxes_b[jj0 + t];
        s_box[t] = c;
        s_area[t] = (c.z - c.x) * (c.w - c.y);
    }
    __syncthreads();
    float4 rb0 = boxes_b[i0];
    float4 rb1 = boxes_b[i1];
    float ar0 = (rb0.z - rb0.x) * (rb0.w - rb0.y);
    float ar1 = (rb1.z - rb1.x) * (rb1.w - rb1.y);
#pragma unroll 4
    for (int j = 0; j < 64; ++j) {
        float4 c = s_box[j];
        float ca = s_area[j];
        int jj = jj0 + j;
        float dy0 = fminf(rb0.z, c.z) - fmaxf(rb0.x, c.x);
        float dx0 = fminf(rb0.w, c.w) - fmaxf(rb0.y, c.y);
        float dy1 = fminf(rb1.z, c.z) - fmaxf(rb1.x, c.x);
        float dx1 = fminf(rb1.w, c.w) - fmaxf(rb1.y, c.y);
        bool ov0 = (dy0 > 0.f) && (dx0 > 0.f) && (jj > i0);
        bool ov1 = (dy1 > 0.f) && (dx1 > 0.f) && (jj > i1);
        if (__any_sync(0xffffffffu, ov0 || ov1)) {
            bool e0 = false, e1 = false;
            if (ov0) {
                float inter = dy0 * dx0;
                float uni = fmaxf(ar0 + ca - inter, 1e-12f);
                e0 = __fdiv_rn(inter, uni) > NMS_THR;
            }
            if (ov1) {
                float inter = dy1 * dx1;
                float uni = fmaxf(ar1 + ca - inter, 1e-12f);
                e1 = __fdiv_rn(inter, uni) > NMS_THR;
            }
            int pos0 = warp_alloc(e0, &g_ecnt[b]);
            if (e0 && pos0 < ECAP)
                g_edges[b * ECAP + pos0] = ((unsigned int)i0 << 16) | (unsigned int)jj;
            int pos1 = warp_alloc(e1, &g_ecnt[b]);
            if (e1 && pos1 < ECAP)
                g_edges[b * ECAP + pos1] = ((unsigned int)i1 << 16) | (unsigned int)jj;
        }
    }
}

// ---------------- 6a: sparse fixpoint NMS on prefix (1 block / batch) ----------------
__global__ void fixpoint_kernel() {
    int b = blockIdx.x, t = threadIdx.x;            // 256 threads
    __shared__ unsigned int  s_edges[ECAP];
    __shared__ unsigned char s_keep[N1];
    __shared__ unsigned char s_supp[N1];
    __shared__ int s_changed;
    __shared__ int s_total;
    int ec = g_ecnt[b];
    if (t == 0) g_ecnt[b] = 0;                      // restore invariant
    if (ec > ECAP) { if (t == 0) g_done[b] = 0; return; }
    for (int i = t; i < ec; i += 256) s_edges[i] = g_edges[b * ECAP + i];
    for (int i = t; i < N1; i += 256) s_keep[i] = 1;
    __syncthreads();
    bool converged = false;
    for (int pass = 0; pass < PASSMAX; ++pass) {
        for (int i = t; i < N1; i += 256) s_supp[i] = 0;
        if (t == 0) s_changed = 0;
        __syncthreads();
        for (int e = t; e < ec; e += 256) {
            unsigned int p = s_edges[e];
            if (s_keep[p >> 16]) s_supp[p & 0xffffu] = 1;
        }
        __syncthreads();
        int ch = 0;
        for (int i = t; i < N1; i += 256) {
            unsigned char nk = (unsigned char)(1 - s_supp[i]);
            if (nk != s_keep[i]) { s_keep[i] = nk; ch = 1; }
        }
        if (ch) s_changed = 1;
        __syncthreads();
        if (!s_changed) { converged = true; break; }
    }
    if (t == 0) s_total = 0;
    __syncthreads();
    int cnt = 0;
    for (int i = t; i < N1; i += 256) {
        g_keep[b * NPRE + i] = s_keep[i];
        cnt += s_keep[i];
    }
    for (int off = 16; off > 0; off >>= 1) cnt += __shfl_down_sync(0xffffffffu, cnt, off);
    if ((t & 31) == 0) atomicAdd(&s_total, cnt);
    __syncthreads();
    int done = (converged && s_total >= NPROP) ? 1 : 0;
    if (t == 0) g_done[b] = done;
    if (done)                                        // tail keep must be 0 when prefix wins
        for (int i = N1 + t; i < NPRE; i += 256) g_keep[b * NPRE + i] = 0;
}

// ---------------- 5b: fallback full mask (persistent, guarded) ----------------
#define RB 47
#define CB 94
__global__ void mask_fb_kernel() {
    int t = threadIdx.x;
    const int T = BATCH * RB * CB;
    for (int tile = blockIdx.x; tile < T; tile += gridDim.x) {
        int b = tile / (RB * CB);
        if (g_done[b]) continue;
        int rb_ = (tile / CB) % RB;
        int cb_ = tile % CB;
        int i0 = rb_ * 128 + t;
        int i1 = i0 + 64;
        u64* mrow = g_mask + (size_t)b * NPRE * NB;
        if (cb_ < 2 * rb_) {
            if (i0 < NPRE) mrow[(size_t)i0 * NB + cb_] = 0ULL;
            if (i1 < NPRE) mrow[(size_t)i1 * NB + cb_] = 0ULL;
            continue;
        }
        __shared__ float4 s_box[64];
        __shared__ float  s_area[64];
        int jj0 = cb_ * 64;
        const float4* boxes_b = g_boxes + b * NPRE;
        {
            int jj = jj0 + t;
            float4 c = (jj < NPRE) ? boxes_b[jj] : make_float4(4.f, 4.f, 3.f, 3.f);
            s_box[t] = c;
            s_area[t] = (c.z - c.x) * (c.w - c.y);
        }
        __syncthreads();
        float4 rb0 = (i0 < NPRE) ? boxes_b[i0] : make_float4(4.f, 4.f, 3.f, 3.f);
        float4 rb1 = (i1 < NPRE) ? boxes_b[i1] : make_float4(4.f, 4.f, 3.f, 3.f);
        float ar0 = (rb0.z - rb0.x) * (rb0.w - rb0.y);
        float ar1 = (rb1.z - rb1.x) * (rb1.w - rb1.y);
        u64 bits0 = 0ULL, bits1 = 0ULL;
#pragma unroll 4
        for (int j = 0; j < 64; ++j) {
            float4 c = s_box[j];
            float ca = s_area[j];
            int jj = jj0 + j;
            float dy0 = fminf(rb0.z, c.z) - fmaxf(rb0.x, c.x);
            float dx0 = fminf(rb0.w, c.w) - fmaxf(rb0.y, c.y);
            float dy1 = fminf(rb1.z, c.z) - fmaxf(rb1.x, c.x);
            float dx1 = fminf(rb1.w, c.w) - fmaxf(rb1.y, c.y);
            bool ov0 = (dy0 > 0.f) && (dx0 > 0.f) && (jj > i0);
            bool ov1 = (dy1 > 0.f) && (dx1 > 0.f) && (jj > i1);
            if (__any_sync(0xffffffffu, ov0 || ov1)) {
                if (ov0) {
                    float inter = dy0 * dx0;
                    float uni = fmaxf(ar0 + ca - inter, 1e-12f);
                    if (__fdiv_rn(inter, uni) > NMS_THR) bits0 |= (1ULL << j);
                }
                if (ov1) {
                    float inter = dy1 * dx1;
                    float uni = fmaxf(ar1 + ca - inter, 1e-12f);
                    if (__fdiv_rn(inter, uni) > NMS_THR) bits1 |= (1ULL << j);
                }
            }
        }
        if (i0 < NPRE) mrow[(size_t)i0 * NB + cb_] = bits0;
        if (i1 < NPRE) mrow[(size_t)i1 * NB + cb_] = bits1;
        __syncthreads();
    }
}

// ---------------- 6b: fallback full scan (guarded) ----------------
__global__ void nms_scan_kernel() {
    int b = blockIdx.x, t = threadIdx.x;            // 32 threads
    if (g_done[b]) return;
    __shared__ u64 ring[16 * 96];
    for (int k = t; k < 16 * 96; k += 32) ring[k] = 0ULL;
    __syncwarp();
    u64 r0 = 0, r1 = 0, r2 = 0;
    unsigned int sbase = (unsigned int)__cvta_generic_to_shared(ring);
    const u64* mrow = g_mask + (size_t)b * NPRE * NB;
    for (int r = 0; r < 16; ++r) {
        const u64* src = mrow + (size_t)r * NB;
        unsigned int dst = sbase + (unsigned int)((r * 96 + t) * 8);
        cp_async8(dst, src + t);
        cp_async8(dst + 32 * 8, src + t + 32);
        if (t < 30) cp_async8(dst + 64 * 8, src + t + 64);
        cp_commit();
    }
    for (int i = 0; i < NPRE; ++i) {
        cp_wait15();
        int wi = i >> 6;
        u64 v = (wi < 32) ? r0 : (wi < 64) ? r1 : r2;
        u64 wv = __shfl_sync(0xffffffffu, v, wi & 31);
        int supp = (int)((wv >> (i & 63)) & 1ULL);
        int slot = i & 15;
        if (!supp) {
            r0 |= ring[slot * 96 + t];
            r1 |= ring[slot * 96 + t + 32];
            r2 |= ring[slot * 96 + t + 64];
        }
        if (t == 0) g_keep[b * NPRE + i] = (unsigned char)(supp ^ 1);
        int r = i + 16;
        if (r < NPRE) {
            const u64* src = mrow + (size_t)r * NB;
            unsigned int dst = sbase + (unsigned int)(((r & 15) * 96 + t) * 8);
            cp_async8(dst, src + t);
            cp_async8(dst + 32 * 8, src + t + 32);
            if (t < 30) cp_async8(dst + 64 * 8, src + t + 64);
        }
        cp_commit();
    }
}

// ---------------- 7: compact kept boxes -> output (ballot scan) ----------------
__global__ void final_kernel(float* __restrict__ out) {
    int b = blockIdx.x, t = threadIdx.x;            // 1024 threads
    for (int k = t; k < NPROP * 4; k += 1024) out[b * NPROP * 4 + k] = 0.f;
    __shared__ int wsum[32];
    __shared__ int s_base;
    if (t == 0) s_base = 0;
    int warp = t >> 5, lane = t & 31;
    __syncthreads();
    for (int tile = 0; tile < 6; ++tile) {
        int i = tile * 1024 + t;
        int kp = (i < NPRE) ? (int)g_keep[b * NPRE + i] : 0;
        unsigned int m = __ballot_sync(0xffffffffu, kp);
        if (lane == 0) wsum[warp] = __popc(m);
        __syncthreads();
        int base = s_base;
        if (warp == 0) {
            int wv = wsum[lane];
#pragma unroll
            for (int o = 1; o < 32; o <<= 1) {
                int u = __shfl_up_sync(0xffffffffu, wv, o);
                if (lane >= o) wv += u;
            }
            wsum[lane] = wv;
        }
        __syncthreads();
        int prev = (warp == 0) ? 0 : wsum[warp - 1];
        int rank = base + prev + __popc(m & ((1u << lane) - 1u));
        if (kp && rank < NPROP)
            ((float4*)out)[b * NPROP + rank] = g_boxes[b * NPRE + i];
        __syncthreads();
        if (t == 0) s_base = base + wsum[31];
        __syncthreads();
    }
}

// ---------------- launch ----------------
extern "C" void kernel_launch(void* const* d_in, const int* in_sizes, int n_in,
                              void* d_out, int out_size) {
    const float* probs   = (const float*)d_in[0];
    const float* bbox    = (const float*)d_in[1];
    const float* anchors = (const float*)d_in[2];
    float* out = (float*)d_out;

    hist_kernel<<<512, 256>>>(probs);
    cutoff_kernel<<<BATCH, 1024>>>();
    compact_kernel<<<512, 256>>>(probs);
    local_sort_kernel<<<32, 256>>>();
    merge_decode_kernel<<<BATCH, 1024>>>(bbox, anchors);
    edge_kernel<<<dim3(12, 24, BATCH), 64>>>();
    fixpoint_kernel<<<BATCH, 256>>>();
    mask_fb_kernel<<<296, 64>>>();                  // near no-op when done
    nms_scan_kernel<<<BATCH, 32>>>();               // no-op when done
    final_kernel<<<BATCH, 1024>>>(out);
}

// round 8
// speedup vs baseline: 7.7178x; 1.1887x over previous
#include <cuda_runtime.h>
#include <cstdint>
#include <math.h>

#define BATCH 8
#define NA 131072            // anchors per batch (2^17)
#define NPRE 6000            // PRE_NMS_LIMIT
#define NB 94                // ceil(NPRE/64)  (fallback mask)
#define NPROP 1000
#define CAND_CAP 8192
#define RUN 1024             // local sort run length
#define HBINS 16384          // key >> 18
#define NMS_THR 0.7f
#define N1 1536              // phase-1 prefix rows
#define ECAP 6144            // edge list capacity per batch
#define PASSMAX 64

typedef unsigned long long u64;

// ---------------- device scratch (static, no allocation) ----------------
// Invariants: g_hist all-zero, g_cand_cnt/g_ecnt zero at entry of each launch
// (zero-init at load; each consumer kernel re-zeroes after use).
__device__ unsigned int  g_hist[BATCH * HBINS];
__device__ int           g_cutbin[BATCH];
__device__ int           g_cand_cnt[BATCH];
__device__ u64           g_cand[BATCH * CAND_CAP];
__device__ float4        g_boxes[BATCH * NPRE];
__device__ int           g_ecnt[BATCH];
__device__ unsigned int  g_edges[BATCH * ECAP];
__device__ u64           g_mask[(size_t)BATCH * NPRE * NB];
__device__ unsigned char g_keep[BATCH * NPRE];
__device__ int           g_done[BATCH];

// ---------------- helpers ----------------
static __device__ __forceinline__ void cp_async8(unsigned int smem, const void* g) {
    asm volatile("cp.async.ca.shared.global [%0], [%1], 8;" :: "r"(smem), "l"(g) : "memory");
}
static __device__ __forceinline__ void cp_commit() {
    asm volatile("cp.async.commit_group;" ::: "memory");
}
static __device__ __forceinline__ void cp_wait15() {
    asm volatile("cp.async.wait_group 15;" ::: "memory");
}
static __device__ __forceinline__ unsigned int score_key(float s) {
    unsigned int u = __float_as_uint(s);
    return u ^ ((unsigned int)((int)u >> 31) | 0x80000000u);
}
static __device__ __forceinline__ int warp_alloc(bool pred, int* ctr) {
    unsigned int m = __ballot_sync(0xffffffffu, pred);
    int lane = threadIdx.x & 31;
    int leader = __ffs(m) - 1;
    int base = 0;
    if (m) {
        if (lane == leader) base = atomicAdd(ctr, __popc(m));
        base = __shfl_sync(0xffffffffu, base, leader);
    }
    return base + __popc(m & ((1u << lane) - 1u));
}
// merge-path partition for DESC-sorted unique keys: first d outputs take a from A
static __device__ __forceinline__ int mpath(const u64* A, int lenA,
                                            const u64* B, int lenB, int d) {
    int lo = d - lenB; if (lo < 0) lo = 0;
    int hi = d < lenA ? d : lenA;
    while (lo < hi) {
        int mid = (lo + hi) >> 1;
        if (A[mid] > B[d - 1 - mid]) lo = mid + 1; else hi = mid;
    }
    return lo;
}
static __device__ __forceinline__ void decode_box(int b, int rank, u64 v,
                                                  const float* __restrict__ bbox,
                                                  const float* __restrict__ anchors) {
    unsigned int a = ~(unsigned int)(v & 0xffffffffULL);
    size_t s4 = (((size_t)b << 17) + a) * 4;
    float d0 = bbox[s4 + 0] * 0.1f;
    float d1 = bbox[s4 + 1] * 0.1f;
    float d2 = bbox[s4 + 2] * 0.2f;
    float d3 = bbox[s4 + 3] * 0.2f;
    float a0 = anchors[s4 + 0], a1 = anchors[s4 + 1];
    float a2 = anchors[s4 + 2], a3 = anchors[s4 + 3];
    float h = a2 - a0, w = a3 - a1;
    float cy = a0 + 0.5f * h + d0 * h;
    float cx = a1 + 0.5f * w + d1 * w;
    float h2 = h * expf(d2);
    float w2 = w * expf(d3);
    float y1 = cy - 0.5f * h2;
    float x1 = cx - 0.5f * w2;
    float y2 = y1 + h2;
    float x2 = x1 + w2;
    y1 = fminf(fmaxf(y1, 0.f), 1.f);
    x1 = fminf(fmaxf(x1, 0.f), 1.f);
    y2 = fminf(fmaxf(y2, 0.f), 1.f);
    x2 = fminf(fmaxf(x2, 0.f), 1.f);
    g_boxes[b * NPRE + rank] = make_float4(y1, x1, y2, x2);
}

// ---------------- 1: histogram ----------------
__global__ void hist_kernel(const float* __restrict__ probs) {
    const float4* p4 = (const float4*)probs;
    int t = threadIdx.x;
    int base = blockIdx.x * 1024;
    int b = base >> 16;
    float4 x[4];
#pragma unroll
    for (int u = 0; u < 4; ++u) x[u] = p4[base + u * 256 + t];
    unsigned int* Hb = g_hist + (size_t)b * HBINS;
#pragma unroll
    for (int u = 0; u < 4; ++u) {
        atomicAdd(&Hb[score_key(x[u].y) >> 18], 1u);
        atomicAdd(&Hb[score_key(x[u].w) >> 18], 1u);
    }
}

// ---------------- 2: cutoff bin (self-cleaning hist) ----------------
__global__ void cutoff_kernel() {
    int b = blockIdx.x, t = threadIdx.x;
    __shared__ unsigned int wtot[32];
    __shared__ unsigned int wsuf[32];
    uint4* H4 = (uint4*)(g_hist + (size_t)b * HBINS);
    int warp = t >> 5, lane = t & 31;
    uint4 h[4];
#pragma unroll
    for (int u = 0; u < 4; ++u) h[u] = H4[t * 4 + u];
    uint4 z = make_uint4(0u, 0u, 0u, 0u);
#pragma unroll
    for (int u = 0; u < 4; ++u) H4[t * 4 + u] = z;
    unsigned int s = 0;
#pragma unroll
    for (int u = 0; u < 4; ++u) s += h[u].x + h[u].y + h[u].z + h[u].w;
    unsigned int ss = s;
#pragma unroll
    for (int o = 1; o < 32; o <<= 1) {
        unsigned int v = __shfl_down_sync(0xffffffffu, ss, o);
        if (lane + o < 32) ss += v;
    }
    if (lane == 0) wtot[warp] = ss;
    __syncthreads();
    if (warp == 0) {
        unsigned int wv = wtot[lane];
#pragma unroll
        for (int o = 1; o < 32; o <<= 1) {
            unsigned int v = __shfl_down_sync(0xffffffffu, wv, o);
            if (lane + o < 32) wv += v;
        }
        wsuf[lane] = wv;
    }
    __syncthreads();
    unsigned int after_warp = (warp < 31) ? wsuf[warp + 1] : 0u;
    unsigned int S = ss + after_warp;
    unsigned int Snext = S - s;
    if (S >= NPRE && Snext < NPRE) {
        unsigned int bins[16];
#pragma unroll
        for (int u = 0; u < 4; ++u) {
            bins[u * 4 + 0] = h[u].x; bins[u * 4 + 1] = h[u].y;
            bins[u * 4 + 2] = h[u].z; bins[u * 4 + 3] = h[u].w;
        }
        unsigned int run = Snext;
        int cut = t * 16;
        for (int k = 15; k >= 0; --k) {
            run += bins[k];
            if (run >= NPRE) { cut = t * 16 + k; break; }
        }
        g_cutbin[b] = cut;
    }
}

// ---------------- 3: compact candidates ----------------
__global__ void compact_kernel(const float* __restrict__ probs) {
    const float4* p4 = (const float4*)probs;
    int t = threadIdx.x;
    int base = blockIdx.x * 1024;
    int b = base >> 16;
    int cut = g_cutbin[b];
    float4 x[4];
#pragma unroll
    for (int u = 0; u < 4; ++u) x[u] = p4[base + u * 256 + t];
#pragma unroll
    for (int u = 0; u < 4; ++u) {
        int j = base + u * 256 + t;
        unsigned int k0 = score_key(x[u].y);
        unsigned int k1 = score_key(x[u].w);
        bool p0 = (int)(k0 >> 18) >= cut;
        bool p1 = (int)(k1 >> 18) >= cut;
        int pos0 = warp_alloc(p0, &g_cand_cnt[b]);
        if (p0 && pos0 < CAND_CAP) {
            unsigned int a = (unsigned int)((2 * j) & (NA - 1));
            g_cand[b * CAND_CAP + pos0] = ((u64)k0 << 32) | (u64)(~a);
        }
        int pos1 = warp_alloc(p1, &g_cand_cnt[b]);
        if (p1 && pos1 < CAND_CAP) {
            unsigned int a = (unsigned int)((2 * j + 1) & (NA - 1));
            g_cand[b * CAND_CAP + pos1] = ((u64)k1 << 32) | (u64)(~a);
        }
    }
}

// ---------------- bitonic building blocks ----------------
static __device__ __forceinline__ void shfl_stage(u64 v[8], int t, int j, int k) {
    int jm = j >> 3;
#pragma unroll
    for (int r = 0; r < 8; ++r) {
        u64 other = __shfl_xor_sync(0xffffffffu, v[r], jm);
        int i = t * 8 + r;
        bool lower = (t & jm) == 0;
        bool desc = ((i & k) == 0);
        bool take_max = (lower == desc);
        u64 mx = v[r] > other ? v[r] : other;
        u64 mn = v[r] > other ? other : v[r];
        v[r] = take_max ? mx : mn;
    }
}
static __device__ __forceinline__ void reg_stage(u64 v[8], int t, int j, int k) {
#pragma unroll
    for (int a = 0; a < 8; ++a) {
        if (!(a & j)) {
            int i = t * 8 + a;
            bool desc = ((i & k) == 0);
            u64 x = v[a], y = v[a + j];
            if (desc ? (x < y) : (x > y)) { v[a] = y; v[a + j] = x; }
        }
    }
}

// ---------------- 4a: local sort of 1024-runs (64 blocks = 8/batch, 128 thr) ----------------
__global__ void local_sort_kernel() {
    __shared__ u64 sh[RUN];
    int blk = blockIdx.x, t = threadIdx.x;
    int b = blk >> 3, chunk = blk & 7;
    int cnt = g_cand_cnt[b]; if (cnt > CAND_CAP) cnt = CAND_CAP;
    u64* run = g_cand + b * CAND_CAP + chunk * RUN;
    int valid = cnt - chunk * RUN;
    u64 v[8];
#pragma unroll
    for (int r = 0; r < 8; ++r) {
        int i = t * 8 + r;
        v[r] = (i < valid) ? run[i] : 0ULL;
    }
    for (int k = 2; k <= 256; k <<= 1) {
        for (int j = k >> 1; j >= 8; j >>= 1) shfl_stage(v, t, j, k);
        if (k > 4) reg_stage(v, t, 4, k);
        if (k > 2) reg_stage(v, t, 2, k);
        reg_stage(v, t, 1, k);
    }
    for (int k = 512; k <= RUN; k <<= 1) {
#pragma unroll
        for (int r = 0; r < 8; ++r) sh[t * 8 + r] = v[r];
        __syncthreads();
        for (int j = k >> 1; j >= 256; j >>= 1) {
#pragma unroll
            for (int w = 0; w < 8; ++w) {
                int i = w * 128 + t;
                int l = i ^ j;
                if (l > i) {
                    u64 x = sh[i], y = sh[l];
                    bool desc = ((i & k) == 0);
                    if (desc ? (x < y) : (x > y)) { sh[i] = y; sh[l] = x; }
                }
            }
            __syncthreads();
        }
#pragma unroll
        for (int r = 0; r < 8; ++r) v[r] = sh[t * 8 + r];
        for (int j = 128; j >= 8; j >>= 1) shfl_stage(v, t, j, k);
        reg_stage(v, t, 4, k);
        reg_stage(v, t, 2, k);
        reg_stage(v, t, 1, k);
    }
#pragma unroll
    for (int r = 0; r < 8; ++r) run[t * 8 + r] = v[r];  // descending run
}

// ---------------- 4b: FAST top-N1 merge-path merge + decode (8 blocks, 256 thr) ----------------
__global__ void fast_merge_decode_kernel(const float* __restrict__ bbox,
                                         const float* __restrict__ anchors) {
    __shared__ u64 bufA[4 * N1];
    __shared__ u64 bufB[2 * N1];
    int b = blockIdx.x, t = threadIdx.x;
    if (t == 0) g_cand_cnt[b] = 0;                  // restore invariant
    const u64* src = g_cand + b * CAND_CAP;
    // L1: 4 merges of (run2m, run2m+1): 1024+1024 -> top N1
    for (int chunk = t; chunk < 4 * (N1 / 8); chunk += 256) {
        int m = chunk / (N1 / 8);
        int d = (chunk % (N1 / 8)) * 8;
        const u64* A = src + (2 * m) * RUN;
        const u64* B = src + (2 * m + 1) * RUN;
        int a = mpath(A, RUN, B, RUN, d);
        int bi = d - a;
        u64* o = bufA + m * N1 + d;
#pragma unroll
        for (int r = 0; r < 8; ++r) {
            bool takeA = (a < RUN) && ((bi >= RUN) || (A[a] > B[bi]));
            o[r] = takeA ? A[a++] : B[bi++];
        }
    }
    __syncthreads();
    // L2: 2 merges of (bufA2m, bufA2m+1): N1+N1 -> top N1
    for (int chunk = t; chunk < 2 * (N1 / 8); chunk += 256) {
        int m = chunk / (N1 / 8);
        int d = (chunk % (N1 / 8)) * 8;
        const u64* A = bufA + (2 * m) * N1;
        const u64* B = bufA + (2 * m + 1) * N1;
        int a = mpath(A, N1, B, N1, d);
        int bi = d - a;
        u64* o = bufB + m * N1 + d;
#pragma unroll
        for (int r = 0; r < 8; ++r) {
            bool takeA = (a < N1) && ((bi >= N1) || (A[a] > B[bi]));
            o[r] = takeA ? A[a++] : B[bi++];
        }
    }
    __syncthreads();
    // L3: final merge -> decode ranks [0, N1)
    if (t < N1 / 8) {
        int d = t * 8;
        const u64* A = bufB;
        const u64* B = bufB + N1;
        int a = mpath(A, N1, B, N1, d);
        int bi = d - a;
#pragma unroll
        for (int r = 0; r < 8; ++r) {
            bool takeA = (a < N1) && ((bi >= N1) || (A[a] > B[bi]));
            u64 v = takeA ? A[a++] : B[bi++];
            decode_box(b, d + r, v, bbox, anchors);
        }
    }
}

// ---------------- 5a: edge emission over first N1 boxes ----------------
__global__ void edge_kernel() {
    int rowblk = blockIdx.x, colblk = blockIdx.y, b = blockIdx.z;
    if (colblk < 2 * rowblk) return;
    int t = threadIdx.x;
    int i0 = rowblk * 128 + t;
    int i1 = i0 + 64;
    __shared__ float4 s_box[64];
    __shared__ float  s_area[64];
    int jj0 = colblk * 64;
    const float4* boxes_b = g_boxes + b * NPRE;
    {
        float4 c = boxes_b[jj0 + t];
        s_box[t] = c;
        s_area[t] = (c.z - c.x) * (c.w - c.y);
    }
    __syncthreads();
    float4 rb0 = boxes_b[i0];
    float4 rb1 = boxes_b[i1];
    float ar0 = (rb0.z - rb0.x) * (rb0.w - rb0.y);
    float ar1 = (rb1.z - rb1.x) * (rb1.w - rb1.y);
#pragma unroll 4
    for (int j = 0; j < 64; ++j) {
        float4 c = s_box[j];
        float ca = s_area[j];
        int jj = jj0 + j;
        float dy0 = fminf(rb0.z, c.z) - fmaxf(rb0.x, c.x);
        float dx0 = fminf(rb0.w, c.w) - fmaxf(rb0.y, c.y);
        float dy1 = fminf(rb1.z, c.z) - fmaxf(rb1.x, c.x);
        float dx1 = fminf(rb1.w, c.w) - fmaxf(rb1.y, c.y);
        bool ov0 = (dy0 > 0.f) && (dx0 > 0.f) && (jj > i0);
        bool ov1 = (dy1 > 0.f) && (dx1 > 0.f) && (jj > i1);
        if (__any_sync(0xffffffffu, ov0 || ov1)) {
            bool e0 = false, e1 = false;
            if (ov0) {
                float inter = dy0 * dx0;
                float uni = fmaxf(ar0 + ca - inter, 1e-12f);
                e0 = __fdiv_rn(inter, uni) > NMS_THR;
            }
            if (ov1) {
                float inter = dy1 * dx1;
                float uni = fmaxf(ar1 + ca - inter, 1e-12f);
                e1 = __fdiv_rn(inter, uni) > NMS_THR;
            }
            int pos0 = warp_alloc(e0, &g_ecnt[b]);
            if (e0 && pos0 < ECAP)
                g_edges[b * ECAP + pos0] = ((unsigned int)i0 << 16) | (unsigned int)jj;
            int pos1 = warp_alloc(e1, &g_ecnt[b]);
            if (e1 && pos1 < ECAP)
                g_edges[b * ECAP + pos1] = ((unsigned int)i1 << 16) | (unsigned int)jj;
        }
    }
}

// ---------------- 6a: sparse fixpoint NMS on prefix (1 block / batch) ----------------
__global__ void fixpoint_kernel() {
    int b = blockIdx.x, t = threadIdx.x;            // 256 threads
    __shared__ unsigned int  s_edges[ECAP];
    __shared__ unsigned char s_keep[N1];
    __shared__ unsigned char s_supp[N1];
    __shared__ int s_changed;
    __shared__ int s_total;
    int ec = g_ecnt[b];
    if (t == 0) g_ecnt[b] = 0;
    if (ec > ECAP) { if (t == 0) g_done[b] = 0; return; }
    for (int i = t; i < ec; i += 256) s_edges[i] = g_edges[b * ECAP + i];
    for (int i = t; i < N1; i += 256) s_keep[i] = 1;
    __syncthreads();
    bool converged = false;
    for (int pass = 0; pass < PASSMAX; ++pass) {
        for (int i = t; i < N1; i += 256) s_supp[i] = 0;
        if (t == 0) s_changed = 0;
        __syncthreads();
        for (int e = t; e < ec; e += 256) {
            unsigned int p = s_edges[e];
            if (s_keep[p >> 16]) s_supp[p & 0xffffu] = 1;
        }
        __syncthreads();
        int ch = 0;
        for (int i = t; i < N1; i += 256) {
            unsigned char nk = (unsigned char)(1 - s_supp[i]);
            if (nk != s_keep[i]) { s_keep[i] = nk; ch = 1; }
        }
        if (ch) s_changed = 1;
        __syncthreads();
        if (!s_changed) { converged = true; break; }
    }
    if (t == 0) s_total = 0;
    __syncthreads();
    int cnt = 0;
    for (int i = t; i < N1; i += 256) {
        g_keep[b * NPRE + i] = s_keep[i];
        cnt += s_keep[i];
    }
    for (int off = 16; off > 0; off >>= 1) cnt += __shfl_down_sync(0xffffffffu, cnt, off);
    if ((t & 31) == 0) atomicAdd(&s_total, cnt);
    __syncthreads();
    int done = (converged && s_total >= NPROP) ? 1 : 0;
    if (t == 0) g_done[b] = done;
    if (done)
        for (int i = N1 + t; i < NPRE; i += 256) g_keep[b * NPRE + i] = 0;
}

// ---------------- 4c: FALLBACK full bitonic merge + decode 6000 (guarded) ----------------
__global__ void full_merge_decode_kernel(const float* __restrict__ bbox,
                                         const float* __restrict__ anchors) {
    int b = blockIdx.x, t = threadIdx.x;            // 1024 threads
    if (g_done[b]) return;
    __shared__ u64 sh[CAND_CAP];
    const u64* src = g_cand + b * CAND_CAP;
    u64 v[8];
    // load; reverse odd 1024-runs to restore the bitonic invariant
#pragma unroll
    for (int r = 0; r < 8; ++r) {
        int g = t * 8 + r;
        int chunk = g >> 10, within = g & 1023;
        int si = (chunk & 1) ? ((chunk << 10) | (1023 - within)) : g;
        v[r] = src[si];
    }
    for (int k = 2048; k <= CAND_CAP; k <<= 1) {
#pragma unroll
        for (int r = 0; r < 8; ++r) sh[t * 8 + r] = v[r];
        __syncthreads();
        for (int j = k >> 1; j >= 256; j >>= 1) {
#pragma unroll
            for (int w = 0; w < 8; ++w) {
                int i = w * 1024 + t;
                int l = i ^ j;
                if (l > i) {
                    u64 x = sh[i], y = sh[l];
                    bool desc = ((i & k) == 0);
                    if (desc ? (x < y) : (x > y)) { sh[i] = y; sh[l] = x; }
                }
            }
            __syncthreads();
        }
#pragma unroll
        for (int r = 0; r < 8; ++r) v[r] = sh[t * 8 + r];
        for (int j = 128; j >= 8; j >>= 1) shfl_stage(v, t, j, k);
        reg_stage(v, t, 4, k);
        reg_stage(v, t, 2, k);
        reg_stage(v, t, 1, k);
    }
#pragma unroll
    for (int r = 0; r < 8; ++r) {
        int rank = t * 8 + r;
        if (rank < NPRE) decode_box(b, rank, v[r], bbox, anchors);
    }
}

// ---------------- 5b: fallback full mask (persistent, guarded) ----------------
#define RB 47
#define CB 94
__global__ void mask_fb_kernel() {
    int t = threadIdx.x;
    const int T = BATCH * RB * CB;
    for (int tile = blockIdx.x; tile < T; tile += gridDim.x) {
        int b = tile / (RB * CB);
        if (g_done[b]) continue;
        int rb_ = (tile / CB) % RB;
        int cb_ = tile % CB;
        int i0 = rb_ * 128 + t;
        int i1 = i0 + 64;
        u64* mrow = g_mask + (size_t)b * NPRE * NB;
        if (cb_ < 2 * rb_) {
            if (i0 < NPRE) mrow[(size_t)i0 * NB + cb_] = 0ULL;
            if (i1 < NPRE) mrow[(size_t)i1 * NB + cb_] = 0ULL;
            continue;
        }
        __shared__ float4 s_box[64];
        __shared__ float  s_area[64];
        int jj0 = cb_ * 64;
        const float4* boxes_b = g_boxes + b * NPRE;
        {
            int jj = jj0 + t;
            float4 c = (jj < NPRE) ? boxes_b[jj] : make_float4(4.f, 4.f, 3.f, 3.f);
            s_box[t] = c;
            s_area[t] = (c.z - c.x) * (c.w - c.y);
        }
        __syncthreads();
        float4 rb0 = (i0 < NPRE) ? boxes_b[i0] : make_float4(4.f, 4.f, 3.f, 3.f);
        float4 rb1 = (i1 < NPRE) ? boxes_b[i1] : make_float4(4.f, 4.f, 3.f, 3.f);
        float ar0 = (rb0.z - rb0.x) * (rb0.w - rb0.y);
        float ar1 = (rb1.z - rb1.x) * (rb1.w - rb1.y);
        u64 bits0 = 0ULL, bits1 = 0ULL;
#pragma unroll 4
        for (int j = 0; j < 64; ++j) {
            float4 c = s_box[j];
            float ca = s_area[j];
            int jj = jj0 + j;
            float dy0 = fminf(rb0.z, c.z) - fmaxf(rb0.x, c.x);
            float dx0 = fminf(rb0.w, c.w) - fmaxf(rb0.y, c.y);
            float dy1 = fminf(rb1.z, c.z) - fmaxf(rb1.x, c.x);
            float dx1 = fminf(rb1.w, c.w) - fmaxf(rb1.y, c.y);
            bool ov0 = (dy0 > 0.f) && (dx0 > 0.f) && (jj > i0);
            bool ov1 = (dy1 > 0.f) && (dx1 > 0.f) && (jj > i1);
            if (__any_sync(0xffffffffu, ov0 || ov1)) {
                if (ov0) {
                    float inter = dy0 * dx0;
                    float uni = fmaxf(ar0 + ca - inter, 1e-12f);
                    if (__fdiv_rn(inter, uni) > NMS_THR) bits0 |= (1ULL << j);
                }
                if (ov1) {
                    float inter = dy1 * dx1;
                    float uni = fmaxf(ar1 + ca - inter, 1e-12f);
                    if (__fdiv_rn(inter, uni) > NMS_THR) bits1 |= (1ULL << j);
                }
            }
        }
        if (i0 < NPRE) mrow[(size_t)i0 * NB + cb_] = bits0;
        if (i1 < NPRE) mrow[(size_t)i1 * NB + cb_] = bits1;
        __syncthreads();
    }
}

// ---------------- 6b: fallback full scan (guarded) ----------------
__global__ void nms_scan_kernel() {
    int b = blockIdx.x, t = threadIdx.x;            // 32 threads
    if (g_done[b]) return;
    __shared__ u64 ring[16 * 96];
    for (int k = t; k < 16 * 96; k += 32) ring[k] = 0ULL;
    __syncwarp();
    u64 r0 = 0, r1 = 0, r2 = 0;
    unsigned int sbase = (unsigned int)__cvta_generic_to_shared(ring);
    const u64* mrow = g_mask + (size_t)b * NPRE * NB;
    for (int r = 0; r < 16; ++r) {
        const u64* src = mrow + (size_t)r * NB;
        unsigned int dst = sbase + (unsigned int)((r * 96 + t) * 8);
        cp_async8(dst, src + t);
        cp_async8(dst + 32 * 8, src + t + 32);
        if (t < 30) cp_async8(dst + 64 * 8, src + t + 64);
        cp_commit();
    }
    for (int i = 0; i < NPRE; ++i) {
        cp_wait15();
        int wi = i >> 6;
        u64 v = (wi < 32) ? r0 : (wi < 64) ? r1 : r2;
        u64 wv = __shfl_sync(0xffffffffu, v, wi & 31);
        int supp = (int)((wv >> (i & 63)) & 1ULL);
        int slot = i & 15;
        if (!supp) {
            r0 |= ring[slot * 96 + t];
            r1 |= ring[slot * 96 + t + 32];
            r2 |= ring[slot * 96 + t + 64];
        }
        if (t == 0) g_keep[b * NPRE + i] = (unsigned char)(supp ^ 1);
        int r = i + 16;
        if (r < NPRE) {
            const u64* src = mrow + (size_t)r * NB;
            unsigned int dst = sbase + (unsigned int)(((r & 15) * 96 + t) * 8);
            cp_async8(dst, src + t);
            cp_async8(dst + 32 * 8, src + t + 32);
            if (t < 30) cp_async8(dst + 64 * 8, src + t + 64);
        }
        cp_commit();
    }
}

// ---------------- 7: compact kept boxes -> output (ballot scan) ----------------
__global__ void final_kernel(float* __restrict__ out) {
    int b = blockIdx.x, t = threadIdx.x;            // 1024 threads
    for (int k = t; k < NPROP * 4; k += 1024) out[b * NPROP * 4 + k] = 0.f;
    __shared__ int wsum[32];
    __shared__ int s_base;
    if (t == 0) s_base = 0;
    int warp = t >> 5, lane = t & 31;
    __syncthreads();
    for (int tile = 0; tile < 6; ++tile) {
        int i = tile * 1024 + t;
        int kp = (i < NPRE) ? (int)g_keep[b * NPRE + i] : 0;
        unsigned int m = __ballot_sync(0xffffffffu, kp);
        if (lane == 0) wsum[warp] = __popc(m);
        __syncthreads();
        int base = s_base;
        if (warp == 0) {
            int wv = wsum[lane];
#pragma unroll
            for (int o = 1; o < 32; o <<= 1) {
                int u = __shfl_up_sync(0xffffffffu, wv, o);
                if (lane >= o) wv += u;
            }
            wsum[lane] = wv;
        }
        __syncthreads();
        int prev = (warp == 0) ? 0 : wsum[warp - 1];
        int rank = base + prev + __popc(m & ((1u << lane) - 1u));
        if (kp && rank < NPROP)
            ((float4*)out)[b * NPROP + rank] = g_boxes[b * NPRE + i];
        __syncthreads();
        if (t == 0) s_base = base + wsum[31];
        __syncthreads();
    }
}

// ---------------- launch ----------------
extern "C" void kernel_launch(void* const* d_in, const int* in_sizes, int n_in,
                              void* d_out, int out_size) {
    const float* probs   = (const float*)d_in[0];
    const float* bbox    = (const float*)d_in[1];
    const float* anchors = (const float*)d_in[2];
    float* out = (float*)d_out;

    hist_kernel<<<512, 256>>>(probs);
    cutoff_kernel<<<BATCH, 1024>>>();
    compact_kernel<<<512, 256>>>(probs);
    local_sort_kernel<<<64, 128>>>();
    fast_merge_decode_kernel<<<BATCH, 256>>>(bbox, anchors);
    edge_kernel<<<dim3(12, 24, BATCH), 64>>>();
    fixpoint_kernel<<<BATCH, 256>>>();
    full_merge_decode_kernel<<<BATCH, 1024>>>(bbox, anchors);  // no-op when done
    mask_fb_kernel<<<296, 64>>>();                              // near no-op when done
    nms_scan_kernel<<<BATCH, 32>>>();                           // no-op when done
    final_kernel<<<BATCH, 1024>>>(out);
}